// round 4
// baseline (speedup 1.0000x reference)
#include <cuda_runtime.h>
#include <cuda_bf16.h>
#include <math.h>

#define BATCH 4
#define NPTS 4995
#define CDIM 128
#define KNN 10
#define IMG 224
#define IMGSZ (IMG*IMG)

// ---------------- K2 tiling ----------------
#define RT 64          // feat1 rows per block
#define CT 128         // feat2 cols per tile
#define ASTRIDE 132    // MUST be multiple of 4 (16B) for float4 smem stores
#define BSTRIDE 132
#define K2SMEM ((RT*ASTRIDE + CT*BSTRIDE + 4*CT)*4)

#define K3CH 2048      // verts chunk for K3/K4

// ---------------- scratch ----------------
__device__ float g_nf1[BATCH*NPTS];
__device__ float g_nf2[BATCH*NPTS];
__device__ float g_verts12[BATCH*NPTS*3];
__device__ int   g_idx11[BATCH*NPTS*KNN];
__device__ float g_img[2][BATCH*IMGSZ];
__device__ unsigned g_pminE[2][BATCH][2];
__device__ unsigned g_pmaxE[2][BATCH][2];
__device__ int g_iminI[2][BATCH][2];
__device__ int g_imaxI[2][BATCH][2];
__device__ double g_self_sum;
__device__ double g_deform_sum;
__device__ double g_img_sum;

// ---------------- helpers ----------------
__device__ __forceinline__ unsigned fenc(float f){
    unsigned u = __float_as_uint(f);
    return (u & 0x80000000u) ? ~u : (u | 0x80000000u);
}
__device__ __forceinline__ float fdec(unsigned u){
    return __uint_as_float((u & 0x80000000u) ? (u ^ 0x80000000u) : ~u);
}
__device__ __forceinline__ float sqrt_approx(float x){
    float y; asm("sqrt.approx.f32 %0, %1;" : "=f"(y) : "f"(x)); return y;
}
__device__ __forceinline__ void block_sum_atomic(float v, double* target){
    __shared__ float red[32];
    int lane = threadIdx.x & 31, w = threadIdx.x >> 5;
    #pragma unroll
    for (int o = 16; o; o >>= 1) v += __shfl_xor_sync(0xffffffffu, v, o);
    if (!lane) red[w] = v;
    __syncthreads();
    if (w == 0){
        int nw = (blockDim.x + 31) >> 5;
        float s = (lane < nw) ? red[lane] : 0.f;
        #pragma unroll
        for (int o = 16; o; o >>= 1) s += __shfl_xor_sync(0xffffffffu, s, o);
        if (!lane) atomicAdd(target, (double)s);
    }
}

// ---------------- K0: init ----------------
__global__ void k_init(){
    int i = blockIdx.x*blockDim.x + threadIdx.x;
    if (i < 2*BATCH*IMGSZ) ((float*)g_img)[i] = 0.0f;
    if (i == 0){ g_self_sum = 0.0; g_deform_sum = 0.0; g_img_sum = 0.0; }
    if (i < 16){
        ((unsigned*)g_pminE)[i] = 0xFFFFFFFFu;
        ((unsigned*)g_pmaxE)[i] = 0u;
        ((int*)g_iminI)[i] = 0x7FFFFFFF;
        ((int*)g_imaxI)[i] = (int)0x80000000;
    }
}

// ---------------- K1: feature row norms ----------------
__global__ void __launch_bounds__(256) k1_norms(const float* __restrict__ f1,
                                                const float* __restrict__ f2){
    int gw = (blockIdx.x*blockDim.x + threadIdx.x) >> 5;
    int lane = threadIdx.x & 31;
    if (gw >= 2*BATCH*NPTS) return;
    const float* src; float* dst; int row;
    if (gw < BATCH*NPTS){ src = f1; dst = g_nf1; row = gw; }
    else { src = f2; dst = g_nf2; row = gw - BATCH*NPTS; }
    float4 v = *(const float4*)(src + (size_t)row*CDIM + lane*4);
    float s = v.x*v.x + v.y*v.y + v.z*v.z + v.w*v.w;
    #pragma unroll
    for (int o = 16; o; o >>= 1) s += __shfl_xor_sync(0xffffffffu, s, o);
    if (!lane) dst[row] = s;
}

// ---------------- K2: fused softmax(-100*cdist) @ verts2 ----------------
__global__ void __launch_bounds__(128, 2)
k2_softmax(const float* __restrict__ feat1, const float* __restrict__ feat2,
           const float* __restrict__ verts2){
    extern __shared__ float sm[];
    float* As   = sm;                    // [RT][ASTRIDE]
    float* Bs   = As + RT*ASTRIDE;       // [CT][BSTRIDE]
    float* nf2s = Bs + CT*BSTRIDE;       // [CT]
    float* v2xs = nf2s + CT;
    float* v2ys = v2xs + CT;
    float* v2zs = v2ys + CT;

    const int t  = threadIdx.x;
    const int tx = t & 15, ty = t >> 4;
    const int b  = blockIdx.y;
    const int n0 = blockIdx.x * RT;
    const float* f1 = feat1 + (size_t)b*NPTS*CDIM;
    const float* f2 = feat2 + (size_t)b*NPTS*CDIM;
    const float* v2 = verts2 + (size_t)b*NPTS*3;

    // stage feat1 tile (row-major, coalesced)
    #pragma unroll
    for (int i = 0; i < 16; i++){
        int lin = i*128 + t;
        int row = lin >> 5, c4 = lin & 31;
        float4 v = make_float4(0.f,0.f,0.f,0.f);
        if (n0 + row < NPTS) v = *(const float4*)(f1 + (size_t)(n0+row)*CDIM + c4*4);
        *(float4*)(As + row*ASTRIDE + c4*4) = v;
    }
    float nf1r[8];
    #pragma unroll
    for (int r = 0; r < 8; r++){
        int n = n0 + ty*8 + r;
        nf1r[r] = (n < NPTS) ? g_nf1[b*NPTS + n] : 0.f;
    }
    float rm[8], rs[8], rx[8], ry[8], rz[8];
    #pragma unroll
    for (int r = 0; r < 8; r++){ rm[r] = -1e30f; rs[r]=0.f; rx[r]=0.f; ry[r]=0.f; rz[r]=0.f; }

    for (int m0 = 0; m0 < NPTS; m0 += CT){
        __syncthreads();
        // stage feat2 tile + per-col data
        #pragma unroll
        for (int i = 0; i < 32; i++){
            int lin = i*128 + t;
            int row = lin >> 5, c4 = lin & 31;
            float4 v = make_float4(0.f,0.f,0.f,0.f);
            if (m0 + row < NPTS) v = *(const float4*)(f2 + (size_t)(m0+row)*CDIM + c4*4);
            *(float4*)(Bs + row*BSTRIDE + c4*4) = v;
        }
        {
            int m = m0 + t;
            bool ok = m < NPTS;
            nf2s[t] = ok ? g_nf2[b*NPTS + m] : 0.f;
            v2xs[t] = ok ? v2[m*3+0] : 0.f;
            v2ys[t] = ok ? v2[m*3+1] : 0.f;
            v2zs[t] = ok ? v2[m*3+2] : 0.f;
        }
        __syncthreads();

        float acc[8][8];
        #pragma unroll
        for (int r = 0; r < 8; r++)
            #pragma unroll
            for (int j = 0; j < 8; j++) acc[r][j] = 0.f;

        #pragma unroll 4
        for (int k = 0; k < CDIM; k++){
            float a[8], bq[8];
            #pragma unroll
            for (int r = 0; r < 8; r++) a[r] = As[(ty*8+r)*ASTRIDE + k];
            #pragma unroll
            for (int j = 0; j < 8; j++) bq[j] = Bs[(j*16+tx)*BSTRIDE + k];
            #pragma unroll
            for (int r = 0; r < 8; r++)
                #pragma unroll
                for (int j = 0; j < 8; j++)
                    acc[r][j] = fmaf(a[r], bq[j], acc[r][j]);
        }

        // epilogue: online softmax with verts2 accumulation
        float nf2c[8], px[8], py[8], pz[8];
        #pragma unroll
        for (int j = 0; j < 8; j++){
            int col = j*16 + tx;
            nf2c[j] = nf2s[col]; px[j] = v2xs[col]; py[j] = v2ys[col]; pz[j] = v2zs[col];
        }
        bool partial = (m0 + CT > NPTS);
        #pragma unroll
        for (int r = 0; r < 8; r++){
            float lg[8];
            float tmax = -1e30f;
            #pragma unroll
            for (int j = 0; j < 8; j++){
                float s = fmaf(-2.f, acc[r][j], nf1r[r] + nf2c[j]);
                s = fmaxf(s, 1e-12f);
                float l = -100.f * sqrt_approx(s);
                if (partial && (m0 + j*16 + tx >= NPTS)) l = -1e30f;
                lg[j] = l;
                tmax = fmaxf(tmax, l);
            }
            float nm = fmaxf(rm[r], tmax);
            float al = __expf(rm[r] - nm);
            rs[r] *= al; rx[r] *= al; ry[r] *= al; rz[r] *= al; rm[r] = nm;
            #pragma unroll
            for (int j = 0; j < 8; j++){
                float w = __expf(lg[j] - nm);
                rs[r] += w;
                rx[r] = fmaf(w, px[j], rx[r]);
                ry[r] = fmaf(w, py[j], ry[r]);
                rz[r] = fmaf(w, pz[j], rz[r]);
            }
        }
    }

    // merge partial softmax states across the 16 tx lanes
    #pragma unroll
    for (int off = 1; off <= 8; off <<= 1){
        #pragma unroll
        for (int r = 0; r < 8; r++){
            float om = __shfl_xor_sync(0xffffffffu, rm[r], off);
            float os = __shfl_xor_sync(0xffffffffu, rs[r], off);
            float ox = __shfl_xor_sync(0xffffffffu, rx[r], off);
            float oy = __shfl_xor_sync(0xffffffffu, ry[r], off);
            float oz = __shfl_xor_sync(0xffffffffu, rz[r], off);
            float nm = fmaxf(rm[r], om);
            float a1 = __expf(rm[r] - nm), a2 = __expf(om - nm);
            rs[r] = rs[r]*a1 + os*a2;
            rx[r] = rx[r]*a1 + ox*a2;
            ry[r] = ry[r]*a1 + oy*a2;
            rz[r] = rz[r]*a1 + oz*a2;
            rm[r] = nm;
        }
    }
    if (tx == 0){
        #pragma unroll
        for (int r = 0; r < 8; r++){
            int n = n0 + ty*8 + r;
            if (n < NPTS){
                float inv = 1.f / rs[r];
                g_verts12[((size_t)b*NPTS + n)*3 + 0] = rx[r]*inv;
                g_verts12[((size_t)b*NPTS + n)*3 + 1] = ry[r]*inv;
                g_verts12[((size_t)b*NPTS + n)*3 + 2] = rz[r]*inv;
            }
        }
    }
}

// ---------------- K3: self_rec = mean min_m ||verts12 - verts2||^2 ----------------
__global__ void __launch_bounds__(256) k3_selfrec(const float* __restrict__ verts2){
    __shared__ float sv[K3CH*3];
    int b = blockIdx.y;
    int part = threadIdx.x & 3;
    int nl = threadIdx.x >> 2;
    int n = blockIdx.x*64 + nl;
    bool valid = n < NPTS;
    float vx=0.f, vy=0.f, vz=0.f;
    if (valid){
        vx = g_verts12[((size_t)b*NPTS + n)*3 + 0];
        vy = g_verts12[((size_t)b*NPTS + n)*3 + 1];
        vz = g_verts12[((size_t)b*NPTS + n)*3 + 2];
    }
    const float* v2 = verts2 + (size_t)b*NPTS*3;
    float best = 3.4e38f;
    for (int m0 = 0; m0 < NPTS; m0 += K3CH){
        int cnt = min(K3CH, NPTS - m0);
        __syncthreads();
        for (int i = threadIdx.x; i < cnt*3; i += 256) sv[i] = v2[m0*3 + i];
        __syncthreads();
        #pragma unroll 4
        for (int i = part; i < cnt; i += 4){
            float dx = vx - sv[3*i], dy = vy - sv[3*i+1], dz = vz - sv[3*i+2];
            float d = fmaf(dx,dx, fmaf(dy,dy, dz*dz));
            best = fminf(best, d);
        }
    }
    best = fminf(best, __shfl_xor_sync(0xffffffffu, best, 1));
    best = fminf(best, __shfl_xor_sync(0xffffffffu, best, 2));
    float contrib = (part == 0 && valid) ? best : 0.f;
    __syncthreads();
    block_sum_atomic(contrib, &g_self_sum);
}

// ---------------- K4: top-10 nearest neighbors of verts1 ----------------
__global__ void __launch_bounds__(256) k4_topk(const float* __restrict__ verts1){
    __shared__ float sv[K3CH*3];
    __shared__ float smval[256][10];
    __shared__ int   smidx[256][10];
    int b = blockIdx.y;
    int part = threadIdx.x & 3;
    int nl = threadIdx.x >> 2;
    int n = blockIdx.x*64 + nl;
    const float* v1 = verts1 + (size_t)b*NPTS*3;
    float vx=0.f, vy=0.f, vz=0.f;
    if (n < NPTS){ vx = v1[3*n]; vy = v1[3*n+1]; vz = v1[3*n+2]; }
    float val[10]; int idx[10];
    #pragma unroll
    for (int q = 0; q < 10; q++){ val[q] = 3.4e38f; idx[q] = 0; }
    for (int m0 = 0; m0 < NPTS; m0 += K3CH){
        int cnt = min(K3CH, NPTS - m0);
        __syncthreads();
        for (int i = threadIdx.x; i < cnt*3; i += 256) sv[i] = v1[m0*3 + i];
        __syncthreads();
        for (int i = part; i < cnt; i += 4){
            float dx = vx - sv[3*i], dy = vy - sv[3*i+1], dz = vz - sv[3*i+2];
            float d = fmaf(dx,dx, fmaf(dy,dy, dz*dz));
            if (d < val[9]){
                float cv = d; int ci = m0 + i;
                #pragma unroll
                for (int q = 0; q < 10; q++){
                    if (cv < val[q]){
                        float tv = val[q]; int ti = idx[q];
                        val[q] = cv; idx[q] = ci; cv = tv; ci = ti;
                    }
                }
            }
        }
    }
    #pragma unroll
    for (int q = 0; q < 10; q++){ smval[threadIdx.x][q] = val[q]; smidx[threadIdx.x][q] = idx[q]; }
    __syncthreads();
    if (part == 0 && n < NPTS){
        int h0=0,h1=0,h2=0,h3=0;
        int base = threadIdx.x;
        int out = (b*NPTS + n)*KNN;
        #pragma unroll
        for (int q = 0; q < 10; q++){
            float b0 = smval[base][h0],   b1 = smval[base+1][h1];
            float b2 = smval[base+2][h2], b3 = smval[base+3][h3];
            float mm = fminf(fminf(b0,b1), fminf(b2,b3));
            int chosen;
            if (mm == b0){ chosen = smidx[base][h0];   h0++; }
            else if (mm == b1){ chosen = smidx[base+1][h1]; h1++; }
            else if (mm == b2){ chosen = smidx[base+2][h2]; h2++; }
            else { chosen = smidx[base+3][h3]; h3++; }
            g_idx11[out + q] = chosen;
        }
    }
}

// ---------------- K5: deform feature MSE ----------------
__global__ void __launch_bounds__(128) k5_deform(const float* __restrict__ feat1){
    int bn = blockIdx.x;
    int b = bn / NPTS, n = bn % NPTS;
    int c = threadIdx.x;
    const float* f1 = feat1 + (size_t)b*NPTS*CDIM;
    float fc = f1[(size_t)n*CDIM + c];
    float acc = 0.f;
    #pragma unroll
    for (int q = 0; q < KNN; q++){
        int m = g_idx11[bn*KNN + q];
        float d = f1[(size_t)m*CDIM + c] - fc;
        acc = fmaf(d, d, acc);
    }
    block_sum_atomic(acc, &g_deform_sum);
}

// ---------------- K6: per-batch xy min/max of points ----------------
__global__ void __launch_bounds__(256) k6_ptminmax(const float* __restrict__ verts2){
    __shared__ float r0[8], r1[8], r2[8], r3[8];
    int tb = blockIdx.y;
    int tensor = tb >> 2, b = tb & 3;
    const float* p = tensor ? (verts2 + (size_t)b*NPTS*3) : (g_verts12 + (size_t)b*NPTS*3);
    int i = blockIdx.x*256 + threadIdx.x;
    float mnx = 1e30f, mny = 1e30f, mxx = -1e30f, mxy = -1e30f;
    if (i < NPTS){ mnx = mxx = p[3*i]; mny = mxy = p[3*i+1]; }
    int lane = threadIdx.x & 31, w = threadIdx.x >> 5;
    #pragma unroll
    for (int o = 16; o; o >>= 1){
        mnx = fminf(mnx, __shfl_xor_sync(0xffffffffu, mnx, o));
        mny = fminf(mny, __shfl_xor_sync(0xffffffffu, mny, o));
        mxx = fmaxf(mxx, __shfl_xor_sync(0xffffffffu, mxx, o));
        mxy = fmaxf(mxy, __shfl_xor_sync(0xffffffffu, mxy, o));
    }
    if (!lane){ r0[w] = mnx; r1[w] = mny; r2[w] = mxx; r3[w] = mxy; }
    __syncthreads();
    if (w == 0){
        mnx = (lane < 8) ? r0[lane] : 1e30f;
        mny = (lane < 8) ? r1[lane] : 1e30f;
        mxx = (lane < 8) ? r2[lane] : -1e30f;
        mxy = (lane < 8) ? r3[lane] : -1e30f;
        #pragma unroll
        for (int o = 4; o; o >>= 1){
            mnx = fminf(mnx, __shfl_xor_sync(0xffffffffu, mnx, o));
            mny = fminf(mny, __shfl_xor_sync(0xffffffffu, mny, o));
            mxx = fmaxf(mxx, __shfl_xor_sync(0xffffffffu, mxx, o));
            mxy = fmaxf(mxy, __shfl_xor_sync(0xffffffffu, mxy, o));
        }
        if (!lane){
            atomicMin(&g_pminE[tensor][b][0], fenc(mnx));
            atomicMin(&g_pminE[tensor][b][1], fenc(mny));
            atomicMax(&g_pmaxE[tensor][b][0], fenc(mxx));
            atomicMax(&g_pmaxE[tensor][b][1], fenc(mxy));
        }
    }
}

// ---------------- K7: per-batch int min/max of grid indices ----------------
__global__ void __launch_bounds__(256) k7_idxminmax(const float* __restrict__ verts2){
    __shared__ int r0[8], r1[8], r2[8], r3[8];
    int tb = blockIdx.y;
    int tensor = tb >> 2, b = tb & 3;
    const float* p = tensor ? (verts2 + (size_t)b*NPTS*3) : (g_verts12 + (size_t)b*NPTS*3);
    float minx = fdec(g_pminE[tensor][b][0]);
    float miny = fdec(g_pminE[tensor][b][1]);
    float maxx = fdec(g_pmaxE[tensor][b][0]);
    float maxy = fdec(g_pmaxE[tensor][b][1]);
    float gs = __fdiv_rn(fmaxf(maxx - minx, maxy - miny), 221.0f);
    int i = blockIdx.x*256 + threadIdx.x;
    int mnx = 0x7FFFFFFF, mny = 0x7FFFFFFF;
    int mxx = (int)0x80000000, mxy = (int)0x80000000;
    if (i < NPTS){
        int ix = (int)floorf(__fdiv_rn(p[3*i]   - minx, gs));
        int iy = (int)floorf(__fdiv_rn(p[3*i+1] - miny, gs));
        mnx = mxx = ix; mny = mxy = iy;
    }
    int lane = threadIdx.x & 31, w = threadIdx.x >> 5;
    #pragma unroll
    for (int o = 16; o; o >>= 1){
        mnx = min(mnx, __shfl_xor_sync(0xffffffffu, mnx, o));
        mny = min(mny, __shfl_xor_sync(0xffffffffu, mny, o));
        mxx = max(mxx, __shfl_xor_sync(0xffffffffu, mxx, o));
        mxy = max(mxy, __shfl_xor_sync(0xffffffffu, mxy, o));
    }
    if (!lane){ r0[w] = mnx; r1[w] = mny; r2[w] = mxx; r3[w] = mxy; }
    __syncthreads();
    if (w == 0){
        mnx = (lane < 8) ? r0[lane] : 0x7FFFFFFF;
        mny = (lane < 8) ? r1[lane] : 0x7FFFFFFF;
        mxx = (lane < 8) ? r2[lane] : (int)0x80000000;
        mxy = (lane < 8) ? r3[lane] : (int)0x80000000;
        #pragma unroll
        for (int o = 4; o; o >>= 1){
            mnx = min(mnx, __shfl_xor_sync(0xffffffffu, mnx, o));
            mny = min(mny, __shfl_xor_sync(0xffffffffu, mny, o));
            mxx = max(mxx, __shfl_xor_sync(0xffffffffu, mxx, o));
            mxy = max(mxy, __shfl_xor_sync(0xffffffffu, mxy, o));
        }
        if (!lane){
            atomicMin(&g_iminI[tensor][b][0], mnx);
            atomicMin(&g_iminI[tensor][b][1], mny);
            atomicMax(&g_imaxI[tensor][b][0], mxx);
            atomicMax(&g_imaxI[tensor][b][1], mxy);
        }
    }
}

// ---------------- K8: scatter z into images ----------------
__global__ void __launch_bounds__(256) k8_scatter(const float* __restrict__ verts2){
    int tb = blockIdx.y;
    int tensor = tb >> 2, b = tb & 3;
    const float* p = tensor ? (verts2 + (size_t)b*NPTS*3) : (g_verts12 + (size_t)b*NPTS*3);
    int i = blockIdx.x*256 + threadIdx.x;
    if (i >= NPTS) return;
    float minx = fdec(g_pminE[tensor][b][0]);
    float miny = fdec(g_pminE[tensor][b][1]);
    float maxx = fdec(g_pmaxE[tensor][b][0]);
    float maxy = fdec(g_pmaxE[tensor][b][1]);
    float gs = __fdiv_rn(fmaxf(maxx - minx, maxy - miny), 221.0f);
    int ix = (int)floorf(__fdiv_rn(p[3*i]   - minx, gs));
    int iy = (int)floorf(__fdiv_rn(p[3*i+1] - miny, gs));
    float z = p[3*i+2];
    int cx = (g_imaxI[tensor][b][0] + g_iminI[tensor][b][0] + 2) >> 1;
    int cy = (g_imaxI[tensor][b][1] + g_iminI[tensor][b][1] + 2) >> 1;
    int ox = 111 - cx, oy = 111 - cy;
    float* img = g_img[tensor] + b*IMGSZ;
    #pragma unroll
    for (int t2 = 0; t2 < 25; t2++){
        int u = ix + (t2/5) - 2 + 1 + ox;
        int v = iy + (t2%5) - 2 + 1 + oy;
        u += (u < 0) - (u > IMG-1);
        v += (v < 0) - (v > IMG-1);
        u = max(0, min(IMG-1, u));
        v = max(0, min(IMG-1, v));
        atomicAdd(&img[u*IMG + v], z);
    }
}

// ---------------- K9: image MSE ----------------
__global__ void __launch_bounds__(256) k9_imgloss(){
    int i = blockIdx.x*256 + threadIdx.x;
    float d = 0.f;
    if (i < BATCH*IMGSZ){
        float a = g_img[0][i], b2 = g_img[1][i];
        float s1 = 1.f/(1.f + __expf(-a));
        float s2 = 1.f/(1.f + __expf(-b2));
        float df = s1 - s2;
        d = df*df;
    }
    block_sum_atomic(d, &g_img_sum);
}

// ---------------- K10: finalize ----------------
__global__ void k10_final(float* out){
    if (threadIdx.x == 0 && blockIdx.x == 0){
        double self_l = g_self_sum / (double)(BATCH*NPTS);
        double def_l  = g_deform_sum / ((double)BATCH*NPTS*KNN*CDIM);
        double img_l  = g_img_sum / ((double)BATCH*IMGSZ);
        out[0] = (float)(self_l + def_l + img_l);
    }
}

// ---------------- launch ----------------
extern "C" void kernel_launch(void* const* d_in, const int* in_sizes, int n_in,
                              void* d_out, int out_size){
    const float* verts1 = (const float*)d_in[0];
    const float* verts2 = (const float*)d_in[1];
    const float* feat1  = (const float*)d_in[2];
    const float* feat2  = (const float*)d_in[3];
    float* out = (float*)d_out;

    cudaFuncSetAttribute(k2_softmax, cudaFuncAttributeMaxDynamicSharedMemorySize, K2SMEM);

    k_init<<<1568, 256>>>();
    k1_norms<<<4995, 256>>>(feat1, feat2);
    k2_softmax<<<dim3((NPTS+RT-1)/RT, BATCH), 128, K2SMEM>>>(feat1, feat2, verts2);
    k3_selfrec<<<dim3((NPTS+63)/64, BATCH), 256>>>(verts2);
    k4_topk<<<dim3((NPTS+63)/64, BATCH), 256>>>(verts1);
    k5_deform<<<BATCH*NPTS, 128>>>(feat1);
    k6_ptminmax<<<dim3((NPTS+255)/256, 2*BATCH), 256>>>(verts2);
    k7_idxminmax<<<dim3((NPTS+255)/256, 2*BATCH), 256>>>(verts2);
    k8_scatter<<<dim3((NPTS+255)/256, 2*BATCH), 256>>>(verts2);
    k9_imgloss<<<(BATCH*IMGSZ+255)/256, 256>>>();
    k10_final<<<1, 32>>>(out);
}

// round 8
// speedup vs baseline: 2.2030x; 2.2030x over previous
#include <cuda_runtime.h>
#include <cuda_bf16.h>
#include <cstdint>
#include <math.h>

typedef unsigned int u32;
typedef unsigned long long u64;

#define BATCH 4
#define NPTS 4995
#define CDIM 128
#define KNN 10
#define IMG 224
#define IMGSZ (IMG*IMG)

#define MT 128
#define NT 128
#define MTILES 40
#define NSPLIT 4
#define CHUNK 1280
#define K2_THREADS 512

#define TILEB 34816
#define AH_SM 0
#define AL_SM 34816
#define BB_SM 69632
#define CI_SM 208896
#define MG_SM 212992
#define K2SMEM 215552

#define K3CH 2048

// ---------------- scratch ----------------
__device__ unsigned short g_f1hi[BATCH*NPTS*CDIM];
__device__ unsigned short g_f1lo[BATCH*NPTS*CDIM];
__device__ unsigned short g_f2hi[BATCH*NPTS*CDIM];
__device__ unsigned short g_f2lo[BATCH*NPTS*CDIM];
__device__ float g_nf1[BATCH*NPTS];
__device__ float g_nf2[BATCH*NPTS];
__device__ float g_pm[BATCH*NPTS*NSPLIT];
__device__ float g_ps[BATCH*NPTS*NSPLIT];
__device__ float g_px[BATCH*NPTS*NSPLIT];
__device__ float g_py[BATCH*NPTS*NSPLIT];
__device__ float g_pz[BATCH*NPTS*NSPLIT];
__device__ float g_verts12[BATCH*NPTS*3];
__device__ int   g_idx11[BATCH*NPTS*KNN];
__device__ float g_img[2][BATCH*IMGSZ];
__device__ unsigned g_pminE[2][BATCH][2];
__device__ unsigned g_pmaxE[2][BATCH][2];
__device__ int g_iminI[2][BATCH][2];
__device__ int g_imaxI[2][BATCH][2];
__device__ double g_self_sum;
__device__ double g_deform_sum;
__device__ double g_img_sum;

// ---------------- generic helpers ----------------
__device__ __forceinline__ unsigned fenc(float f){
    unsigned uu = __float_as_uint(f);
    return (uu & 0x80000000u) ? ~uu : (uu | 0x80000000u);
}
__device__ __forceinline__ float fdec(unsigned uu){
    return __uint_as_float((uu & 0x80000000u) ? (uu ^ 0x80000000u) : ~uu);
}
__device__ __forceinline__ float sqrt_approx(float x){
    float y; asm("sqrt.approx.f32 %0, %1;" : "=f"(y) : "f"(x)); return y;
}
__device__ __forceinline__ void block_sum_atomic(float v, double* target){
    __shared__ float red[32];
    int lane = threadIdx.x & 31, w = threadIdx.x >> 5;
    #pragma unroll
    for (int o = 16; o; o >>= 1) v += __shfl_xor_sync(0xffffffffu, v, o);
    if (!lane) red[w] = v;
    __syncthreads();
    if (w == 0){
        int nw = (blockDim.x + 31) >> 5;
        float s = (lane < nw) ? red[lane] : 0.f;
        #pragma unroll
        for (int o = 16; o; o >>= 1) s += __shfl_xor_sync(0xffffffffu, s, o);
        if (!lane) atomicAdd(target, (double)s);
    }
}
__device__ __forceinline__ u32 smem_u32(const void* p){
    u32 a;
    asm("{ .reg .u64 t; cvta.to.shared.u64 t, %1; cvt.u32.u64 %0, t; }" : "=r"(a) : "l"(p));
    return a;
}

// ---------------- mma.sync / ldmatrix wrappers ----------------
__device__ __forceinline__ void ldsm_x4(u32* r, u32 addr){
    asm volatile("ldmatrix.sync.aligned.m8n8.x4.shared.b16 {%0,%1,%2,%3}, [%4];"
        : "=r"(r[0]), "=r"(r[1]), "=r"(r[2]), "=r"(r[3]) : "r"(addr));
}
__device__ __forceinline__ void ldsm_x2(u32* r, u32 addr){
    asm volatile("ldmatrix.sync.aligned.m8n8.x2.shared.b16 {%0,%1}, [%2];"
        : "=r"(r[0]), "=r"(r[1]) : "r"(addr));
}
__device__ __forceinline__ void mma_bf16(float* d, const u32* a, u32 b0, u32 b1){
    asm volatile(
        "mma.sync.aligned.m16n8k16.row.col.f32.bf16.bf16.f32 "
        "{%0,%1,%2,%3}, {%4,%5,%6,%7}, {%8,%9}, {%0,%1,%2,%3};"
        : "+f"(d[0]), "+f"(d[1]), "+f"(d[2]), "+f"(d[3])
        : "r"(a[0]), "r"(a[1]), "r"(a[2]), "r"(a[3]), "r"(b0), "r"(b1));
}

// ---------------- K0: init ----------------
__global__ void k_init(){
    int i = blockIdx.x*blockDim.x + threadIdx.x;
    if (i < 2*BATCH*IMGSZ) ((float*)g_img)[i] = 0.0f;
    if (i == 0){ g_self_sum = 0.0; g_deform_sum = 0.0; g_img_sum = 0.0; }
    if (i < 16){
        ((unsigned*)g_pminE)[i] = 0xFFFFFFFFu;
        ((unsigned*)g_pmaxE)[i] = 0u;
        ((int*)g_iminI)[i] = 0x7FFFFFFF;
        ((int*)g_imaxI)[i] = (int)0x80000000;
    }
}

// ---------------- Kprep: double-bf16 split ----------------
__global__ void __launch_bounds__(256) kprep(const float* __restrict__ f1,
                                             const float* __restrict__ f2){
    const int half = BATCH*NPTS*CDIM/4;
    int i = blockIdx.x*256 + threadIdx.x;
    if (i >= 2*half) return;
    bool second = i >= half;
    int j = second ? i - half : i;
    float4 v = ((const float4*)(second ? f2 : f1))[j];
    unsigned short* hi = second ? g_f2hi : g_f1hi;
    unsigned short* lo = second ? g_f2lo : g_f1lo;
    float vv[4]; vv[0]=v.x; vv[1]=v.y; vv[2]=v.z; vv[3]=v.w;
    unsigned short hu[4], lu[4];
    #pragma unroll
    for (int c = 0; c < 4; c++){
        __nv_bfloat16 h = __float2bfloat16_rn(vv[c]);
        float r = vv[c] - __bfloat162float(h);
        __nv_bfloat16 l = __float2bfloat16_rn(r);
        hu[c] = __bfloat16_as_ushort(h);
        lu[c] = __bfloat16_as_ushort(l);
    }
    ((uint2*)hi)[j] = make_uint2((u32)hu[0] | ((u32)hu[1] << 16),
                                 (u32)hu[2] | ((u32)hu[3] << 16));
    ((uint2*)lo)[j] = make_uint2((u32)lu[0] | ((u32)lu[1] << 16),
                                 (u32)lu[2] | ((u32)lu[3] << 16));
}

// ---------------- K1: feature row norms ----------------
__global__ void __launch_bounds__(256) k1_norms(const float* __restrict__ f1,
                                                const float* __restrict__ f2){
    int gw = (blockIdx.x*blockDim.x + threadIdx.x) >> 5;
    int lane = threadIdx.x & 31;
    if (gw >= 2*BATCH*NPTS) return;
    const float* src; float* dst; int row;
    if (gw < BATCH*NPTS){ src = f1; dst = g_nf1; row = gw; }
    else { src = f2; dst = g_nf2; row = gw - BATCH*NPTS; }
    float4 v = *(const float4*)(src + (size_t)row*CDIM + lane*4);
    float s = v.x*v.x + v.y*v.y + v.z*v.z + v.w*v.w;
    #pragma unroll
    for (int o = 16; o; o >>= 1) s += __shfl_xor_sync(0xffffffffu, s, o);
    if (!lane) dst[row] = s;
}

// ---------------- K2: HMMA fused softmax(-100*cdist) @ verts2 ----------------
__global__ void __launch_bounds__(K2_THREADS)
k2_softmax_mma(const float* __restrict__ verts2){
    extern __shared__ char smem[];
    const int tid = threadIdx.x;
    const int wid = tid >> 5, lane = tid & 31;
    const int b = blockIdx.z, split = blockIdx.y, mt = blockIdx.x;
    const int n0 = mt * MT;
    const int cs = split * CHUNK;
    const int ce = min(cs + CHUNK, NPTS);
    const int T = (ce - cs + NT - 1) / NT;
    const size_t bofs = (size_t)b * NPTS;
    const float* v2 = verts2 + bofs * 3;
    u32 sb = smem_u32(smem);

    // stage A tile (hi & lo)
    for (int i = tid; i < 2048; i += K2_THREADS){
        int row = i >> 4, c8 = i & 15;
        int n = n0 + row;
        uint4 vh = make_uint4(0u,0u,0u,0u);
        uint4 vl = make_uint4(0u,0u,0u,0u);
        if (n < NPTS){
            vh = *(const uint4*)(g_f1hi + ((bofs + n) << 7) + (c8 << 3));
            vl = *(const uint4*)(g_f1lo + ((bofs + n) << 7) + (c8 << 3));
        }
        *(uint4*)(smem + AH_SM + row*272 + c8*16) = vh;
        *(uint4*)(smem + AL_SM + row*272 + c8*16) = vl;
    }
    // stage B tile 0 + colinfo 0
    {
        int m0 = cs;
        for (int i = tid; i < 2048; i += K2_THREADS){
            int row = i >> 4, c8 = i & 15;
            int m = m0 + row;
            uint4 vh = make_uint4(0u,0u,0u,0u);
            uint4 vl = make_uint4(0u,0u,0u,0u);
            if (m < ce){
                vh = *(const uint4*)(g_f2hi + ((bofs + m) << 7) + (c8 << 3));
                vl = *(const uint4*)(g_f2lo + ((bofs + m) << 7) + (c8 << 3));
            }
            *(uint4*)(smem + BB_SM + row*272 + c8*16) = vh;
            *(uint4*)(smem + BB_SM + TILEB + row*272 + c8*16) = vl;
        }
        if (tid < 128){
            int m = m0 + tid;
            float4 ci;
            if (m < ce){ ci.x = g_nf2[bofs+m]; ci.y = v2[m*3]; ci.z = v2[m*3+1]; ci.w = v2[m*3+2]; }
            else { ci.x = 1e30f; ci.y = 0.f; ci.z = 0.f; ci.w = 0.f; }
            *(float4*)(smem + CI_SM + tid*16) = ci;
        }
    }
    __syncthreads();

    const int rslice = wid & 7;      // 16-row slice within 128
    const int chalf  = wid >> 3;     // column half (0: cols 0-63, 1: 64-127)
    const u32 aRowOff = (u32)((rslice*16 + (lane & 15)) * 272 + (lane >> 4) * 16);
    const u32 aHa = sb + AH_SM + aRowOff;
    const u32 aLa = sb + AL_SM + aRowOff;
    const u32 bRowOff = (u32)((chalf*64 + (lane & 7)) * 272 + ((lane >> 3) & 1) * 16);

    float nf10 = 0.f, nf11 = 0.f;
    const int r0g = n0 + rslice*16 + (lane >> 2);
    if (r0g < NPTS) nf10 = g_nf1[bofs + r0g];
    if (r0g + 8 < NPTS) nf11 = g_nf1[bofs + r0g + 8];

    float rm0=-1e30f, rs0=0.f, rx0=0.f, ry0=0.f, rz0=0.f;
    float rm1=-1e30f, rs1=0.f, rx1=0.f, ry1=0.f, rz1=0.f;

    for (int t = 0; t < T; t++){
        // prefetch B(t+1) into other buffer
        if (t + 1 < T){
            int m0 = cs + (t+1)*NT;
            int nb = (t+1) & 1;
            for (int i = tid; i < 2048; i += K2_THREADS){
                int row = i >> 4, c8 = i & 15;
                int m = m0 + row;
                uint4 vh = make_uint4(0u,0u,0u,0u);
                uint4 vl = make_uint4(0u,0u,0u,0u);
                if (m < ce){
                    vh = *(const uint4*)(g_f2hi + ((bofs + m) << 7) + (c8 << 3));
                    vl = *(const uint4*)(g_f2lo + ((bofs + m) << 7) + (c8 << 3));
                }
                *(uint4*)(smem + BB_SM + nb*69632 + row*272 + c8*16) = vh;
                *(uint4*)(smem + BB_SM + nb*69632 + TILEB + row*272 + c8*16) = vl;
            }
            if (tid < 128){
                int m = m0 + tid;
                float4 ci;
                if (m < ce){ ci.x = g_nf2[bofs+m]; ci.y = v2[m*3]; ci.z = v2[m*3+1]; ci.w = v2[m*3+2]; }
                else { ci.x = 1e30f; ci.y = 0.f; ci.z = 0.f; ci.w = 0.f; }
                *(float4*)(smem + CI_SM + nb*2048 + tid*16) = ci;
            }
        }

        // MMA over K=128 (8 k-steps, 3 bf16-split terms)
        float acc[32];
        #pragma unroll
        for (int i = 0; i < 32; i++) acc[i] = 0.f;
        const u32 bHa = sb + BB_SM + (u32)((t & 1)*69632) + bRowOff;
        #pragma unroll
        for (int ks = 0; ks < 8; ks++){
            u32 ah[4], al[4];
            ldsm_x4(ah, aHa + ks*32);
            ldsm_x4(al, aLa + ks*32);
            #pragma unroll
            for (int f = 0; f < 8; f++){
                u32 bh[2], bl[2];
                u32 baddr = bHa + (u32)(f*2176 + ks*32);
                ldsm_x2(bh, baddr);
                ldsm_x2(bl, baddr + TILEB);
                mma_bf16(acc + f*4, ah, bh[0], bh[1]);
                mma_bf16(acc + f*4, ah, bl[0], bl[1]);
                mma_bf16(acc + f*4, al, bh[0], bh[1]);
            }
        }

        // online softmax epilogue (registers -> per-thread state, 2 rows)
        const char* cib = smem + CI_SM + (t & 1)*2048;
        float tm0 = -1e30f, tm1 = -1e30f;
        #pragma unroll
        for (int f = 0; f < 8; f++){
            int n = chalf*64 + f*8 + (lane & 3)*2;
            float c0x = *(const float*)(cib + n*16);
            float c1x = *(const float*)(cib + n*16 + 16);
            float s0 = fmaxf(fmaf(-2.f, acc[f*4+0], nf10 + c0x), 1e-12f);
            float s1 = fmaxf(fmaf(-2.f, acc[f*4+1], nf10 + c1x), 1e-12f);
            float s2 = fmaxf(fmaf(-2.f, acc[f*4+2], nf11 + c0x), 1e-12f);
            float s3 = fmaxf(fmaf(-2.f, acc[f*4+3], nf11 + c1x), 1e-12f);
            acc[f*4+0] = -100.f*sqrt_approx(s0);
            acc[f*4+1] = -100.f*sqrt_approx(s1);
            acc[f*4+2] = -100.f*sqrt_approx(s2);
            acc[f*4+3] = -100.f*sqrt_approx(s3);
            tm0 = fmaxf(tm0, fmaxf(acc[f*4+0], acc[f*4+1]));
            tm1 = fmaxf(tm1, fmaxf(acc[f*4+2], acc[f*4+3]));
        }
        float nm0 = fmaxf(rm0, tm0), nm1 = fmaxf(rm1, tm1);
        float sc0 = __expf(rm0 - nm0), sc1 = __expf(rm1 - nm1);
        rs0 *= sc0; rx0 *= sc0; ry0 *= sc0; rz0 *= sc0; rm0 = nm0;
        rs1 *= sc1; rx1 *= sc1; ry1 *= sc1; rz1 *= sc1; rm1 = nm1;
        #pragma unroll
        for (int f = 0; f < 8; f++){
            int n = chalf*64 + f*8 + (lane & 3)*2;
            float4 c0 = *(const float4*)(cib + n*16);
            float4 c1 = *(const float4*)(cib + n*16 + 16);
            float w0 = __expf(acc[f*4+0] - nm0);
            float w1 = __expf(acc[f*4+1] - nm0);
            float w2 = __expf(acc[f*4+2] - nm1);
            float w3 = __expf(acc[f*4+3] - nm1);
            rs0 += w0 + w1; rs1 += w2 + w3;
            rx0 = fmaf(w0, c0.y, fmaf(w1, c1.y, rx0));
            ry0 = fmaf(w0, c0.z, fmaf(w1, c1.z, ry0));
            rz0 = fmaf(w0, c0.w, fmaf(w1, c1.w, rz0));
            rx1 = fmaf(w2, c0.y, fmaf(w3, c1.y, rx1));
            ry1 = fmaf(w2, c0.z, fmaf(w3, c1.z, ry1));
            rz1 = fmaf(w2, c0.w, fmaf(w3, c1.w, rz1));
        }
        __syncthreads();
    }

    // merge across the 4 lanes of each row quad
    #pragma unroll
    for (int o = 1; o <= 2; o <<= 1){
        float om = __shfl_xor_sync(0xffffffffu, rm0, o);
        float os = __shfl_xor_sync(0xffffffffu, rs0, o);
        float ox = __shfl_xor_sync(0xffffffffu, rx0, o);
        float oy = __shfl_xor_sync(0xffffffffu, ry0, o);
        float oz = __shfl_xor_sync(0xffffffffu, rz0, o);
        float nm = fmaxf(rm0, om);
        float e1 = __expf(rm0 - nm), e2 = __expf(om - nm);
        rs0 = rs0*e1 + os*e2; rx0 = rx0*e1 + ox*e2;
        ry0 = ry0*e1 + oy*e2; rz0 = rz0*e1 + oz*e2; rm0 = nm;
        om = __shfl_xor_sync(0xffffffffu, rm1, o);
        os = __shfl_xor_sync(0xffffffffu, rs1, o);
        ox = __shfl_xor_sync(0xffffffffu, rx1, o);
        oy = __shfl_xor_sync(0xffffffffu, ry1, o);
        oz = __shfl_xor_sync(0xffffffffu, rz1, o);
        nm = fmaxf(rm1, om);
        e1 = __expf(rm1 - nm); e2 = __expf(om - nm);
        rs1 = rs1*e1 + os*e2; rx1 = rx1*e1 + ox*e2;
        ry1 = ry1*e1 + oy*e2; rz1 = rz1*e1 + oz*e2; rm1 = nm;
    }

    // merge column halves through smem, write split partials
    float* mg = (float*)(smem + MG_SM);
    int rl0 = rslice*16 + (lane >> 2);
    if (chalf == 1 && (lane & 3) == 0){
        mg[rl0*5+0] = rm0; mg[rl0*5+1] = rs0; mg[rl0*5+2] = rx0; mg[rl0*5+3] = ry0; mg[rl0*5+4] = rz0;
        mg[(rl0+8)*5+0] = rm1; mg[(rl0+8)*5+1] = rs1; mg[(rl0+8)*5+2] = rx1; mg[(rl0+8)*5+3] = ry1; mg[(rl0+8)*5+4] = rz1;
    }
    __syncthreads();
    if (chalf == 0 && (lane & 3) == 0){
        float m2 = mg[rl0*5+0], s2 = mg[rl0*5+1], x2 = mg[rl0*5+2], y2 = mg[rl0*5+3], z2 = mg[rl0*5+4];
        float nm = fmaxf(rm0, m2);
        float e1 = __expf(rm0 - nm), e2 = __expf(m2 - nm);
        float S = rs0*e1 + s2*e2, X = rx0*e1 + x2*e2, Y = ry0*e1 + y2*e2, Z = rz0*e1 + z2*e2;
        int n = n0 + rl0;
        if (n < NPTS){
            size_t pi = (bofs + n)*NSPLIT + split;
            g_pm[pi] = nm; g_ps[pi] = S; g_px[pi] = X; g_py[pi] = Y; g_pz[pi] = Z;
        }
        m2 = mg[(rl0+8)*5+0]; s2 = mg[(rl0+8)*5+1]; x2 = mg[(rl0+8)*5+2]; y2 = mg[(rl0+8)*5+3]; z2 = mg[(rl0+8)*5+4];
        nm = fmaxf(rm1, m2);
        e1 = __expf(rm1 - nm); e2 = __expf(m2 - nm);
        S = rs1*e1 + s2*e2; X = rx1*e1 + x2*e2; Y = ry1*e1 + y2*e2; Z = rz1*e1 + z2*e2;
        n = n0 + rl0 + 8;
        if (n < NPTS){
            size_t pi = (bofs + n)*NSPLIT + split;
            g_pm[pi] = nm; g_ps[pi] = S; g_px[pi] = X; g_py[pi] = Y; g_pz[pi] = Z;
        }
    }
}

// ---------------- K2b: merge splits -> verts12 ----------------
__global__ void __launch_bounds__(256) k2b_merge(){
    int i = blockIdx.x*256 + threadIdx.x;
    if (i >= BATCH*NPTS) return;
    float m = -1e30f, s = 0.f, x = 0.f, y = 0.f, z = 0.f;
    #pragma unroll
    for (int sp = 0; sp < NSPLIT; sp++){
        size_t pi = (size_t)i*NSPLIT + sp;
        float m2 = g_pm[pi], s2 = g_ps[pi], x2 = g_px[pi], y2 = g_py[pi], z2 = g_pz[pi];
        float nm = fmaxf(m, m2);
        float a1 = __expf(m - nm), a2 = __expf(m2 - nm);
        s = s*a1 + s2*a2; x = x*a1 + x2*a2; y = y*a1 + y2*a2; z = z*a1 + z2*a2;
        m = nm;
    }
    float inv = 1.f / s;
    g_verts12[(size_t)i*3 + 0] = x*inv;
    g_verts12[(size_t)i*3 + 1] = y*inv;
    g_verts12[(size_t)i*3 + 2] = z*inv;
}

// ---------------- K3: self_rec ----------------
__global__ void __launch_bounds__(256) k3_selfrec(const float* __restrict__ verts2){
    __shared__ float sv[K3CH*3];
    int b = blockIdx.y;
    int part = threadIdx.x & 3;
    int nl = threadIdx.x >> 2;
    int n = blockIdx.x*64 + nl;
    bool valid = n < NPTS;
    float vx=0.f, vy=0.f, vz=0.f;
    if (valid){
        vx = g_verts12[((size_t)b*NPTS + n)*3 + 0];
        vy = g_verts12[((size_t)b*NPTS + n)*3 + 1];
        vz = g_verts12[((size_t)b*NPTS + n)*3 + 2];
    }
    const float* v2 = verts2 + (size_t)b*NPTS*3;
    float best = 3.4e38f;
    for (int m0 = 0; m0 < NPTS; m0 += K3CH){
        int cnt = min(K3CH, NPTS - m0);
        __syncthreads();
        for (int i = threadIdx.x; i < cnt*3; i += 256) sv[i] = v2[m0*3 + i];
        __syncthreads();
        #pragma unroll 4
        for (int i = part; i < cnt; i += 4){
            float dx = vx - sv[3*i], dy = vy - sv[3*i+1], dz = vz - sv[3*i+2];
            float d = fmaf(dx,dx, fmaf(dy,dy, dz*dz));
            best = fminf(best, d);
        }
    }
    best = fminf(best, __shfl_xor_sync(0xffffffffu, best, 1));
    best = fminf(best, __shfl_xor_sync(0xffffffffu, best, 2));
    float contrib = (part == 0 && valid) ? best : 0.f;
    __syncthreads();
    block_sum_atomic(contrib, &g_self_sum);
}

// ---------------- K4: top-10 nearest neighbors ----------------
__global__ void __launch_bounds__(256) k4_topk(const float* __restrict__ verts1){
    __shared__ float sv[K3CH*3];
    __shared__ float smval[256][10];
    __shared__ int   smidx[256][10];
    int b = blockIdx.y;
    int part = threadIdx.x & 3;
    int nl = threadIdx.x >> 2;
    int n = blockIdx.x*64 + nl;
    const float* v1 = verts1 + (size_t)b*NPTS*3;
    float vx=0.f, vy=0.f, vz=0.f;
    if (n < NPTS){ vx = v1[3*n]; vy = v1[3*n+1]; vz = v1[3*n+2]; }
    float val[10]; int idx[10];
    #pragma unroll
    for (int q = 0; q < 10; q++){ val[q] = 3.4e38f; idx[q] = 0; }
    for (int m0 = 0; m0 < NPTS; m0 += K3CH){
        int cnt = min(K3CH, NPTS - m0);
        __syncthreads();
        for (int i = threadIdx.x; i < cnt*3; i += 256) sv[i] = v1[m0*3 + i];
        __syncthreads();
        for (int i = part; i < cnt; i += 4){
            float dx = vx - sv[3*i], dy = vy - sv[3*i+1], dz = vz - sv[3*i+2];
            float d = fmaf(dx,dx, fmaf(dy,dy, dz*dz));
            if (d < val[9]){
                float cv = d; int ci = m0 + i;
                #pragma unroll
                for (int q = 0; q < 10; q++){
                    if (cv < val[q]){
                        float tv = val[q]; int ti = idx[q];
                        val[q] = cv; idx[q] = ci; cv = tv; ci = ti;
                    }
                }
            }
        }
    }
    #pragma unroll
    for (int q = 0; q < 10; q++){ smval[threadIdx.x][q] = val[q]; smidx[threadIdx.x][q] = idx[q]; }
    __syncthreads();
    if (part == 0 && n < NPTS){
        int h0=0,h1=0,h2=0,h3=0;
        int base = threadIdx.x;
        int out = (b*NPTS + n)*KNN;
        #pragma unroll
        for (int q = 0; q < 10; q++){
            float b0 = smval[base][h0],   b1 = smval[base+1][h1];
            float b2 = smval[base+2][h2], b3 = smval[base+3][h3];
            float mm = fminf(fminf(b0,b1), fminf(b2,b3));
            int chosen;
            if (mm == b0){ chosen = smidx[base][h0];   h0++; }
            else if (mm == b1){ chosen = smidx[base+1][h1]; h1++; }
            else if (mm == b2){ chosen = smidx[base+2][h2]; h2++; }
            else { chosen = smidx[base+3][h3]; h3++; }
            g_idx11[out + q] = chosen;
        }
    }
}

// ---------------- K5: deform feature MSE ----------------
__global__ void __launch_bounds__(128) k5_deform(const float* __restrict__ feat1){
    int bn = blockIdx.x;
    int b = bn / NPTS, n = bn % NPTS;
    int c = threadIdx.x;
    const float* f1 = feat1 + (size_t)b*NPTS*CDIM;
    float fc = f1[(size_t)n*CDIM + c];
    float acc = 0.f;
    #pragma unroll
    for (int q = 0; q < KNN; q++){
        int m = g_idx11[bn*KNN + q];
        float d = f1[(size_t)m*CDIM + c] - fc;
        acc = fmaf(d, d, acc);
    }
    block_sum_atomic(acc, &g_deform_sum);
}

// ---------------- K6: per-batch xy min/max ----------------
__global__ void __launch_bounds__(256) k6_ptminmax(const float* __restrict__ verts2){
    __shared__ float r0[8], r1[8], r2[8], r3[8];
    int tb = blockIdx.y;
    int tensor = tb >> 2, b = tb & 3;
    const float* p = tensor ? (verts2 + (size_t)b*NPTS*3) : (g_verts12 + (size_t)b*NPTS*3);
    int i = blockIdx.x*256 + threadIdx.x;
    float mnx = 1e30f, mny = 1e30f, mxx = -1e30f, mxy = -1e30f;
    if (i < NPTS){ mnx = mxx = p[3*i]; mny = mxy = p[3*i+1]; }
    int lane = threadIdx.x & 31, w = threadIdx.x >> 5;
    #pragma unroll
    for (int o = 16; o; o >>= 1){
        mnx = fminf(mnx, __shfl_xor_sync(0xffffffffu, mnx, o));
        mny = fminf(mny, __shfl_xor_sync(0xffffffffu, mny, o));
        mxx = fmaxf(mxx, __shfl_xor_sync(0xffffffffu, mxx, o));
        mxy = fmaxf(mxy, __shfl_xor_sync(0xffffffffu, mxy, o));
    }
    if (!lane){ r0[w] = mnx; r1[w] = mny; r2[w] = mxx; r3[w] = mxy; }
    __syncthreads();
    if (w == 0){
        mnx = (lane < 8) ? r0[lane] : 1e30f;
        mny = (lane < 8) ? r1[lane] : 1e30f;
        mxx = (lane < 8) ? r2[lane] : -1e30f;
        mxy = (lane < 8) ? r3[lane] : -1e30f;
        #pragma unroll
        for (int o = 4; o; o >>= 1){
            mnx = fminf(mnx, __shfl_xor_sync(0xffffffffu, mnx, o));
            mny = fminf(mny, __shfl_xor_sync(0xffffffffu, mny, o));
            mxx = fmaxf(mxx, __shfl_xor_sync(0xffffffffu, mxx, o));
            mxy = fmaxf(mxy, __shfl_xor_sync(0xffffffffu, mxy, o));
        }
        if (!lane){
            atomicMin(&g_pminE[tensor][b][0], fenc(mnx));
            atomicMin(&g_pminE[tensor][b][1], fenc(mny));
            atomicMax(&g_pmaxE[tensor][b][0], fenc(mxx));
            atomicMax(&g_pmaxE[tensor][b][1], fenc(mxy));
        }
    }
}

// ---------------- K7: per-batch int min/max of grid indices ----------------
__global__ void __launch_bounds__(256) k7_idxminmax(const float* __restrict__ verts2){
    __shared__ int r0[8], r1[8], r2[8], r3[8];
    int tb = blockIdx.y;
    int tensor = tb >> 2, b = tb & 3;
    const float* p = tensor ? (verts2 + (size_t)b*NPTS*3) : (g_verts12 + (size_t)b*NPTS*3);
    float minx = fdec(g_pminE[tensor][b][0]);
    float miny = fdec(g_pminE[tensor][b][1]);
    float maxx = fdec(g_pmaxE[tensor][b][0]);
    float maxy = fdec(g_pmaxE[tensor][b][1]);
    float gs = __fdiv_rn(fmaxf(maxx - minx, maxy - miny), 221.0f);
    int i = blockIdx.x*256 + threadIdx.x;
    int mnx = 0x7FFFFFFF, mny = 0x7FFFFFFF;
    int mxx = (int)0x80000000, mxy = (int)0x80000000;
    if (i < NPTS){
        int ix = (int)floorf(__fdiv_rn(p[3*i]   - minx, gs));
        int iy = (int)floorf(__fdiv_rn(p[3*i+1] - miny, gs));
        mnx = mxx = ix; mny = mxy = iy;
    }
    int lane = threadIdx.x & 31, w = threadIdx.x >> 5;
    #pragma unroll
    for (int o = 16; o; o >>= 1){
        mnx = min(mnx, __shfl_xor_sync(0xffffffffu, mnx, o));
        mny = min(mny, __shfl_xor_sync(0xffffffffu, mny, o));
        mxx = max(mxx, __shfl_xor_sync(0xffffffffu, mxx, o));
        mxy = max(mxy, __shfl_xor_sync(0xffffffffu, mxy, o));
    }
    if (!lane){ r0[w] = mnx; r1[w] = mny; r2[w] = mxx; r3[w] = mxy; }
    __syncthreads();
    if (w == 0){
        mnx = (lane < 8) ? r0[lane] : 0x7FFFFFFF;
        mny = (lane < 8) ? r1[lane] : 0x7FFFFFFF;
        mxx = (lane < 8) ? r2[lane] : (int)0x80000000;
        mxy = (lane < 8) ? r3[lane] : (int)0x80000000;
        #pragma unroll
        for (int o = 4; o; o >>= 1){
            mnx = min(mnx, __shfl_xor_sync(0xffffffffu, mnx, o));
            mny = min(mny, __shfl_xor_sync(0xffffffffu, mny, o));
            mxx = max(mxx, __shfl_xor_sync(0xffffffffu, mxx, o));
            mxy = max(mxy, __shfl_xor_sync(0xffffffffu, mxy, o));
        }
        if (!lane){
            atomicMin(&g_iminI[tensor][b][0], mnx);
            atomicMin(&g_iminI[tensor][b][1], mny);
            atomicMax(&g_imaxI[tensor][b][0], mxx);
            atomicMax(&g_imaxI[tensor][b][1], mxy);
        }
    }
}

// ---------------- K8: scatter z into images ----------------
__global__ void __launch_bounds__(256) k8_scatter(const float* __restrict__ verts2){
    int tb = blockIdx.y;
    int tensor = tb >> 2, b = tb & 3;
    const float* p = tensor ? (verts2 + (size_t)b*NPTS*3) : (g_verts12 + (size_t)b*NPTS*3);
    int i = blockIdx.x*256 + threadIdx.x;
    if (i >= NPTS) return;
    float minx = fdec(g_pminE[tensor][b][0]);
    float miny = fdec(g_pminE[tensor][b][1]);
    float maxx = fdec(g_pmaxE[tensor][b][0]);
    float maxy = fdec(g_pmaxE[tensor][b][1]);
    float gs = __fdiv_rn(fmaxf(maxx - minx, maxy - miny), 221.0f);
    int ix = (int)floorf(__fdiv_rn(p[3*i]   - minx, gs));
    int iy = (int)floorf(__fdiv_rn(p[3*i+1] - miny, gs));
    float z = p[3*i+2];
    int cx = (g_imaxI[tensor][b][0] + g_iminI[tensor][b][0] + 2) >> 1;
    int cy = (g_imaxI[tensor][b][1] + g_iminI[tensor][b][1] + 2) >> 1;
    int ox = 111 - cx, oy = 111 - cy;
    float* img = g_img[tensor] + b*IMGSZ;
    #pragma unroll
    for (int t2 = 0; t2 < 25; t2++){
        int du = t2 / 5;
        int dv = t2 - du*5;
        int uu = ix + du - 1 + ox;
        int vv = iy + dv - 1 + oy;
        uu += (uu < 0) - (uu > IMG-1);
        vv += (vv < 0) - (vv > IMG-1);
        uu = max(0, min(IMG-1, uu));
        vv = max(0, min(IMG-1, vv));
        atomicAdd(&img[uu*IMG + vv], z);
    }
}

// ---------------- K9: image MSE ----------------
__global__ void __launch_bounds__(256) k9_imgloss(){
    int i = blockIdx.x*256 + threadIdx.x;
    float d = 0.f;
    if (i < BATCH*IMGSZ){
        float a = g_img[0][i], b2 = g_img[1][i];
        float s1 = 1.f/(1.f + __expf(-a));
        float s2 = 1.f/(1.f + __expf(-b2));
        float df = s1 - s2;
        d = df*df;
    }
    block_sum_atomic(d, &g_img_sum);
}

// ---------------- K10: finalize ----------------
__global__ void k10_final(float* out){
    if (threadIdx.x == 0 && blockIdx.x == 0){
        double self_l = g_self_sum / (double)(BATCH*NPTS);
        double def_l  = g_deform_sum / ((double)BATCH*NPTS*KNN*CDIM);
        double img_l  = g_img_sum / ((double)BATCH*IMGSZ);
        out[0] = (float)(self_l + img_l + def_l);
    }
}

// ---------------- launch ----------------
extern "C" void kernel_launch(void* const* d_in, const int* in_sizes, int n_in,
                              void* d_out, int out_size){
    const float* verts1 = (const float*)d_in[0];
    const float* verts2 = (const float*)d_in[1];
    const float* feat1  = (const float*)d_in[2];
    const float* feat2  = (const float*)d_in[3];
    float* out = (float*)d_out;

    cudaFuncSetAttribute(k2_softmax_mma, cudaFuncAttributeMaxDynamicSharedMemorySize, K2SMEM);

    k_init<<<1568, 256>>>();
    kprep<<<4995, 256>>>(feat1, feat2);
    k1_norms<<<4995, 256>>>(feat1, feat2);
    k2_softmax_mma<<<dim3(MTILES, NSPLIT, BATCH), K2_THREADS, K2SMEM>>>(verts2);
    k2b_merge<<<(BATCH*NPTS + 255)/256, 256>>>();
    k3_selfrec<<<dim3((NPTS+63)/64, BATCH), 256>>>(verts2);
    k4_topk<<<dim3((NPTS+63)/64, BATCH), 256>>>(verts1);
    k5_deform<<<BATCH*NPTS, 128>>>(feat1);
    k6_ptminmax<<<dim3((NPTS+255)/256, 2*BATCH), 256>>>(verts2);
    k7_idxminmax<<<dim3((NPTS+255)/256, 2*BATCH), 256>>>(verts2);
    k8_scatter<<<dim3((NPTS+255)/256, 2*BATCH), 256>>>(verts2);
    k9_imgloss<<<(BATCH*IMGSZ+255)/256, 256>>>();
    k10_final<<<1, 32>>>(out);
}

// round 9
// speedup vs baseline: 2.3132x; 1.0500x over previous
#include <cuda_runtime.h>
#include <cuda_bf16.h>
#include <cstdint>
#include <math.h>

typedef unsigned int u32;
typedef unsigned long long u64;

#define BATCH 4
#define NPTS 4995
#define CDIM 128
#define KNN 10
#define IMG 224
#define IMGSZ (IMG*IMG)

#define MT 128
#define NT 128
#define MTILES 40
#define NSPLIT 4
#define CHUNK 1280
#define K2_THREADS 512

#define TILEB 34816
#define AH_SM 0
#define AL_SM 34816
#define BB_SM 69632
#define CI_SM 208896
#define MG_SM 212992
#define K2SMEM 215552

#define K3CH 2048

// ---------------- scratch ----------------
__device__ unsigned short g_f1hi[BATCH*NPTS*CDIM];
__device__ unsigned short g_f1lo[BATCH*NPTS*CDIM];
__device__ unsigned short g_f2hi[BATCH*NPTS*CDIM];
__device__ unsigned short g_f2lo[BATCH*NPTS*CDIM];
__device__ float g_nf1[BATCH*NPTS];
__device__ float g_nf2[BATCH*NPTS];
__device__ float g_pm[BATCH*NPTS*NSPLIT];
__device__ float g_ps[BATCH*NPTS*NSPLIT];
__device__ float g_px[BATCH*NPTS*NSPLIT];
__device__ float g_py[BATCH*NPTS*NSPLIT];
__device__ float g_pz[BATCH*NPTS*NSPLIT];
__device__ float g_verts12[BATCH*NPTS*3];
__device__ int   g_idx11[BATCH*NPTS*KNN];
__device__ float g_img[2][BATCH*IMGSZ];
__device__ unsigned g_pminE[2][BATCH][2];
__device__ unsigned g_pmaxE[2][BATCH][2];
__device__ int g_iminI[2][BATCH][2];
__device__ int g_imaxI[2][BATCH][2];
__device__ double g_self_sum;
__device__ double g_deform_sum;
__device__ double g_img_sum;

// ---------------- generic helpers ----------------
__device__ __forceinline__ unsigned fenc(float f){
    unsigned uu = __float_as_uint(f);
    return (uu & 0x80000000u) ? ~uu : (uu | 0x80000000u);
}
__device__ __forceinline__ float fdec(unsigned uu){
    return __uint_as_float((uu & 0x80000000u) ? (uu ^ 0x80000000u) : ~uu);
}
__device__ __forceinline__ float sqrt_approx(float x){
    float y; asm("sqrt.approx.f32 %0, %1;" : "=f"(y) : "f"(x)); return y;
}
__device__ __forceinline__ void block_sum_atomic(float v, double* target){
    __shared__ float red[32];
    int lane = threadIdx.x & 31, w = threadIdx.x >> 5;
    #pragma unroll
    for (int o = 16; o; o >>= 1) v += __shfl_xor_sync(0xffffffffu, v, o);
    if (!lane) red[w] = v;
    __syncthreads();
    if (w == 0){
        int nw = (blockDim.x + 31) >> 5;
        float s = (lane < nw) ? red[lane] : 0.f;
        #pragma unroll
        for (int o = 16; o; o >>= 1) s += __shfl_xor_sync(0xffffffffu, s, o);
        if (!lane) atomicAdd(target, (double)s);
    }
}
__device__ __forceinline__ u32 smem_u32(const void* p){
    u32 a;
    asm("{ .reg .u64 t; cvta.to.shared.u64 t, %1; cvt.u32.u64 %0, t; }" : "=r"(a) : "l"(p));
    return a;
}

// ---------------- mma.sync / ldmatrix wrappers ----------------
__device__ __forceinline__ void ldsm_x4(u32* r, u32 addr){
    asm volatile("ldmatrix.sync.aligned.m8n8.x4.shared.b16 {%0,%1,%2,%3}, [%4];"
        : "=r"(r[0]), "=r"(r[1]), "=r"(r[2]), "=r"(r[3]) : "r"(addr));
}
__device__ __forceinline__ void mma_bf16(float* d, const u32* a, u32 b0, u32 b1){
    asm volatile(
        "mma.sync.aligned.m16n8k16.row.col.f32.bf16.bf16.f32 "
        "{%0,%1,%2,%3}, {%4,%5,%6,%7}, {%8,%9}, {%0,%1,%2,%3};"
        : "+f"(d[0]), "+f"(d[1]), "+f"(d[2]), "+f"(d[3])
        : "r"(a[0]), "r"(a[1]), "r"(a[2]), "r"(a[3]), "r"(b0), "r"(b1));
}

// ---------------- K0: init ----------------
__global__ void k_init(){
    int i = blockIdx.x*blockDim.x + threadIdx.x;
    if (i < 2*BATCH*IMGSZ) ((float*)g_img)[i] = 0.0f;
    if (i == 0){ g_self_sum = 0.0; g_deform_sum = 0.0; g_img_sum = 0.0; }
    if (i < 16){
        ((unsigned*)g_pminE)[i] = 0xFFFFFFFFu;
        ((unsigned*)g_pmaxE)[i] = 0u;
        ((int*)g_iminI)[i] = 0x7FFFFFFF;
        ((int*)g_imaxI)[i] = (int)0x80000000;
    }
}

// ---------------- Kprep: double-bf16 split ----------------
__global__ void __launch_bounds__(256) kprep(const float* __restrict__ f1,
                                             const float* __restrict__ f2){
    const int half = BATCH*NPTS*CDIM/4;
    int i = blockIdx.x*256 + threadIdx.x;
    if (i >= 2*half) return;
    bool second = i >= half;
    int j = second ? i - half : i;
    float4 v = ((const float4*)(second ? f2 : f1))[j];
    unsigned short* hi = second ? g_f2hi : g_f1hi;
    unsigned short* lo = second ? g_f2lo : g_f1lo;
    float vv[4]; vv[0]=v.x; vv[1]=v.y; vv[2]=v.z; vv[3]=v.w;
    unsigned short hu[4], lu[4];
    #pragma unroll
    for (int c = 0; c < 4; c++){
        __nv_bfloat16 h = __float2bfloat16_rn(vv[c]);
        float r = vv[c] - __bfloat162float(h);
        __nv_bfloat16 l = __float2bfloat16_rn(r);
        hu[c] = __bfloat16_as_ushort(h);
        lu[c] = __bfloat16_as_ushort(l);
    }
    ((uint2*)hi)[j] = make_uint2((u32)hu[0] | ((u32)hu[1] << 16),
                                 (u32)hu[2] | ((u32)hu[3] << 16));
    ((uint2*)lo)[j] = make_uint2((u32)lu[0] | ((u32)lu[1] << 16),
                                 (u32)lu[2] | ((u32)lu[3] << 16));
}

// ---------------- K1: feature row norms ----------------
__global__ void __launch_bounds__(256) k1_norms(const float* __restrict__ f1,
                                                const float* __restrict__ f2){
    int gw = (blockIdx.x*blockDim.x + threadIdx.x) >> 5;
    int lane = threadIdx.x & 31;
    if (gw >= 2*BATCH*NPTS) return;
    const float* src; float* dst; int row;
    if (gw < BATCH*NPTS){ src = f1; dst = g_nf1; row = gw; }
    else { src = f2; dst = g_nf2; row = gw - BATCH*NPTS; }
    float4 v = *(const float4*)(src + (size_t)row*CDIM + lane*4);
    float s = v.x*v.x + v.y*v.y + v.z*v.z + v.w*v.w;
    #pragma unroll
    for (int o = 16; o; o >>= 1) s += __shfl_xor_sync(0xffffffffu, s, o);
    if (!lane) dst[row] = s;
}

// ---------------- K2: HMMA fused softmax(-100*cdist) @ verts2 ----------------
__global__ void __launch_bounds__(K2_THREADS)
k2_softmax_mma(const float* __restrict__ verts2){
    extern __shared__ char smem[];
    const int tid = threadIdx.x;
    const int wid = tid >> 5, lane = tid & 31;
    const int b = blockIdx.z, split = blockIdx.y, mt = blockIdx.x;
    const int n0 = mt * MT;
    const int cs = split * CHUNK;
    const int ce = min(cs + CHUNK, NPTS);
    const int T = (ce - cs + NT - 1) / NT;
    const size_t bofs = (size_t)b * NPTS;
    const float* v2 = verts2 + bofs * 3;
    u32 sb = smem_u32(smem);

    // stage A tile (hi & lo)
    for (int i = tid; i < 2048; i += K2_THREADS){
        int row = i >> 4, c8 = i & 15;
        int n = n0 + row;
        uint4 vh = make_uint4(0u,0u,0u,0u);
        uint4 vl = make_uint4(0u,0u,0u,0u);
        if (n < NPTS){
            vh = *(const uint4*)(g_f1hi + ((bofs + n) << 7) + (c8 << 3));
            vl = *(const uint4*)(g_f1lo + ((bofs + n) << 7) + (c8 << 3));
        }
        *(uint4*)(smem + AH_SM + row*272 + c8*16) = vh;
        *(uint4*)(smem + AL_SM + row*272 + c8*16) = vl;
    }
    // stage B tile 0 + colinfo 0
    {
        int m0 = cs;
        for (int i = tid; i < 2048; i += K2_THREADS){
            int row = i >> 4, c8 = i & 15;
            int m = m0 + row;
            uint4 vh = make_uint4(0u,0u,0u,0u);
            uint4 vl = make_uint4(0u,0u,0u,0u);
            if (m < ce){
                vh = *(const uint4*)(g_f2hi + ((bofs + m) << 7) + (c8 << 3));
                vl = *(const uint4*)(g_f2lo + ((bofs + m) << 7) + (c8 << 3));
            }
            *(uint4*)(smem + BB_SM + row*272 + c8*16) = vh;
            *(uint4*)(smem + BB_SM + TILEB + row*272 + c8*16) = vl;
        }
        if (tid < 128){
            int m = m0 + tid;
            float4 ci;
            if (m < ce){ ci.x = g_nf2[bofs+m]; ci.y = v2[m*3]; ci.z = v2[m*3+1]; ci.w = v2[m*3+2]; }
            else { ci.x = 1e30f; ci.y = 0.f; ci.z = 0.f; ci.w = 0.f; }
            *(float4*)(smem + CI_SM + tid*16) = ci;
        }
    }
    __syncthreads();

    const int rslice = wid & 7;      // 16-row slice within 128
    const int chalf  = wid >> 3;     // column half (0: cols 0-63, 1: 64-127)
    const u32 aRowOff = (u32)((rslice*16 + (lane & 15)) * 272 + (lane >> 4) * 16);
    const u32 aHa = sb + AH_SM + aRowOff;
    const u32 aLa = sb + AL_SM + aRowOff;
    // x4 B layout: lanes 0-7: rows r..r+7 k-half0; 8-15: same rows k-half1;
    //              16-23: rows r+8..r+15 k-half0; 24-31: k-half1
    const u32 bRowOff4 = (u32)((chalf*64 + (lane & 7) + ((lane >> 4) << 3)) * 272
                             + (((lane >> 3) & 1) << 4));

    float nf10 = 0.f, nf11 = 0.f;
    const int r0g = n0 + rslice*16 + (lane >> 2);
    if (r0g < NPTS) nf10 = g_nf1[bofs + r0g];
    if (r0g + 8 < NPTS) nf11 = g_nf1[bofs + r0g + 8];

    float rm0=-1e30f, rs0=0.f, rx0=0.f, ry0=0.f, rz0=0.f;
    float rm1=-1e30f, rs1=0.f, rx1=0.f, ry1=0.f, rz1=0.f;

    for (int t = 0; t < T; t++){
        // prefetch B(t+1) into other buffer
        if (t + 1 < T){
            int m0 = cs + (t+1)*NT;
            int nb = (t+1) & 1;
            for (int i = tid; i < 2048; i += K2_THREADS){
                int row = i >> 4, c8 = i & 15;
                int m = m0 + row;
                uint4 vh = make_uint4(0u,0u,0u,0u);
                uint4 vl = make_uint4(0u,0u,0u,0u);
                if (m < ce){
                    vh = *(const uint4*)(g_f2hi + ((bofs + m) << 7) + (c8 << 3));
                    vl = *(const uint4*)(g_f2lo + ((bofs + m) << 7) + (c8 << 3));
                }
                *(uint4*)(smem + BB_SM + nb*69632 + row*272 + c8*16) = vh;
                *(uint4*)(smem + BB_SM + nb*69632 + TILEB + row*272 + c8*16) = vl;
            }
            if (tid < 128){
                int m = m0 + tid;
                float4 ci;
                if (m < ce){ ci.x = g_nf2[bofs+m]; ci.y = v2[m*3]; ci.z = v2[m*3+1]; ci.w = v2[m*3+2]; }
                else { ci.x = 1e30f; ci.y = 0.f; ci.z = 0.f; ci.w = 0.f; }
                *(float4*)(smem + CI_SM + nb*2048 + tid*16) = ci;
            }
        }

        // MMA over K=128 (8 k-steps, 3 bf16-split terms), B via x4 ldsm over f-pairs
        float acc[32];
        #pragma unroll
        for (int i = 0; i < 32; i++) acc[i] = 0.f;
        const u32 bHa = sb + BB_SM + (u32)((t & 1)*69632) + bRowOff4;
        #pragma unroll
        for (int ks = 0; ks < 8; ks++){
            u32 ah[4], al[4];
            ldsm_x4(ah, aHa + ks*32);
            ldsm_x4(al, aLa + ks*32);
            #pragma unroll
            for (int fp = 0; fp < 4; fp++){
                u32 bh[4], bl[4];
                u32 baddr = bHa + (u32)(fp*4352 + ks*32);
                ldsm_x4(bh, baddr);
                ldsm_x4(bl, baddr + TILEB);
                mma_bf16(acc + fp*8,     ah, bh[0], bh[1]);
                mma_bf16(acc + fp*8,     ah, bl[0], bl[1]);
                mma_bf16(acc + fp*8,     al, bh[0], bh[1]);
                mma_bf16(acc + fp*8 + 4, ah, bh[2], bh[3]);
                mma_bf16(acc + fp*8 + 4, ah, bl[2], bl[3]);
                mma_bf16(acc + fp*8 + 4, al, bh[2], bh[3]);
            }
        }

        // online softmax epilogue (registers -> per-thread state, 2 rows)
        const char* cib = smem + CI_SM + (t & 1)*2048;
        float tm0 = -1e30f, tm1 = -1e30f;
        #pragma unroll
        for (int f = 0; f < 8; f++){
            int n = chalf*64 + f*8 + (lane & 3)*2;
            float c0x = *(const float*)(cib + n*16);
            float c1x = *(const float*)(cib + n*16 + 16);
            float s0 = fmaxf(fmaf(-2.f, acc[f*4+0], nf10 + c0x), 1e-12f);
            float s1 = fmaxf(fmaf(-2.f, acc[f*4+1], nf10 + c1x), 1e-12f);
            float s2 = fmaxf(fmaf(-2.f, acc[f*4+2], nf11 + c0x), 1e-12f);
            float s3 = fmaxf(fmaf(-2.f, acc[f*4+3], nf11 + c1x), 1e-12f);
            acc[f*4+0] = -100.f*sqrt_approx(s0);
            acc[f*4+1] = -100.f*sqrt_approx(s1);
            acc[f*4+2] = -100.f*sqrt_approx(s2);
            acc[f*4+3] = -100.f*sqrt_approx(s3);
            tm0 = fmaxf(tm0, fmaxf(acc[f*4+0], acc[f*4+1]));
            tm1 = fmaxf(tm1, fmaxf(acc[f*4+2], acc[f*4+3]));
        }
        float nm0 = fmaxf(rm0, tm0), nm1 = fmaxf(rm1, tm1);
        float sc0 = __expf(rm0 - nm0), sc1 = __expf(rm1 - nm1);
        rs0 *= sc0; rx0 *= sc0; ry0 *= sc0; rz0 *= sc0; rm0 = nm0;
        rs1 *= sc1; rx1 *= sc1; ry1 *= sc1; rz1 *= sc1; rm1 = nm1;
        #pragma unroll
        for (int f = 0; f < 8; f++){
            int n = chalf*64 + f*8 + (lane & 3)*2;
            float4 c0 = *(const float4*)(cib + n*16);
            float4 c1 = *(const float4*)(cib + n*16 + 16);
            float w0 = __expf(acc[f*4+0] - nm0);
            float w1 = __expf(acc[f*4+1] - nm0);
            float w2 = __expf(acc[f*4+2] - nm1);
            float w3 = __expf(acc[f*4+3] - nm1);
            rs0 += w0 + w1; rs1 += w2 + w3;
            rx0 = fmaf(w0, c0.y, fmaf(w1, c1.y, rx0));
            ry0 = fmaf(w0, c0.z, fmaf(w1, c1.z, ry0));
            rz0 = fmaf(w0, c0.w, fmaf(w1, c1.w, rz0));
            rx1 = fmaf(w2, c0.y, fmaf(w3, c1.y, rx1));
            ry1 = fmaf(w2, c0.z, fmaf(w3, c1.z, ry1));
            rz1 = fmaf(w2, c0.w, fmaf(w3, c1.w, rz1));
        }
        __syncthreads();
    }

    // merge across the 4 lanes of each row quad
    #pragma unroll
    for (int o = 1; o <= 2; o <<= 1){
        float om = __shfl_xor_sync(0xffffffffu, rm0, o);
        float os = __shfl_xor_sync(0xffffffffu, rs0, o);
        float ox = __shfl_xor_sync(0xffffffffu, rx0, o);
        float oy = __shfl_xor_sync(0xffffffffu, ry0, o);
        float oz = __shfl_xor_sync(0xffffffffu, rz0, o);
        float nm = fmaxf(rm0, om);
        float e1 = __expf(rm0 - nm), e2 = __expf(om - nm);
        rs0 = rs0*e1 + os*e2; rx0 = rx0*e1 + ox*e2;
        ry0 = ry0*e1 + oy*e2; rz0 = rz0*e1 + oz*e2; rm0 = nm;
        om = __shfl_xor_sync(0xffffffffu, rm1, o);
        os = __shfl_xor_sync(0xffffffffu, rs1, o);
        ox = __shfl_xor_sync(0xffffffffu, rx1, o);
        oy = __shfl_xor_sync(0xffffffffu, ry1, o);
        oz = __shfl_xor_sync(0xffffffffu, rz1, o);
        nm = fmaxf(rm1, om);
        e1 = __expf(rm1 - nm); e2 = __expf(om - nm);
        rs1 = rs1*e1 + os*e2; rx1 = rx1*e1 + ox*e2;
        ry1 = ry1*e1 + oy*e2; rz1 = rz1*e1 + oz*e2; rm1 = nm;
    }

    // merge column halves through smem, write split partials
    float* mg = (float*)(smem + MG_SM);
    int rl0 = rslice*16 + (lane >> 2);
    if (chalf == 1 && (lane & 3) == 0){
        mg[rl0*5+0] = rm0; mg[rl0*5+1] = rs0; mg[rl0*5+2] = rx0; mg[rl0*5+3] = ry0; mg[rl0*5+4] = rz0;
        mg[(rl0+8)*5+0] = rm1; mg[(rl0+8)*5+1] = rs1; mg[(rl0+8)*5+2] = rx1; mg[(rl0+8)*5+3] = ry1; mg[(rl0+8)*5+4] = rz1;
    }
    __syncthreads();
    if (chalf == 0 && (lane & 3) == 0){
        float m2 = mg[rl0*5+0], s2 = mg[rl0*5+1], x2 = mg[rl0*5+2], y2 = mg[rl0*5+3], z2 = mg[rl0*5+4];
        float nm = fmaxf(rm0, m2);
        float e1 = __expf(rm0 - nm), e2 = __expf(m2 - nm);
        float S = rs0*e1 + s2*e2, X = rx0*e1 + x2*e2, Y = ry0*e1 + y2*e2, Z = rz0*e1 + z2*e2;
        int n = n0 + rl0;
        if (n < NPTS){
            size_t pi = (bofs + n)*NSPLIT + split;
            g_pm[pi] = nm; g_ps[pi] = S; g_px[pi] = X; g_py[pi] = Y; g_pz[pi] = Z;
        }
        m2 = mg[(rl0+8)*5+0]; s2 = mg[(rl0+8)*5+1]; x2 = mg[(rl0+8)*5+2]; y2 = mg[(rl0+8)*5+3]; z2 = mg[(rl0+8)*5+4];
        nm = fmaxf(rm1, m2);
        e1 = __expf(rm1 - nm); e2 = __expf(m2 - nm);
        S = rs1*e1 + s2*e2; X = rx1*e1 + x2*e2; Y = ry1*e1 + y2*e2; Z = rz1*e1 + z2*e2;
        n = n0 + rl0 + 8;
        if (n < NPTS){
            size_t pi = (bofs + n)*NSPLIT + split;
            g_pm[pi] = nm; g_ps[pi] = S; g_px[pi] = X; g_py[pi] = Y; g_pz[pi] = Z;
        }
    }
}

// ---------------- K2b: merge splits -> verts12 ----------------
__global__ void __launch_bounds__(256) k2b_merge(){
    int i = blockIdx.x*256 + threadIdx.x;
    if (i >= BATCH*NPTS) return;
    float m = -1e30f, s = 0.f, x = 0.f, y = 0.f, z = 0.f;
    #pragma unroll
    for (int sp = 0; sp < NSPLIT; sp++){
        size_t pi = (size_t)i*NSPLIT + sp;
        float m2 = g_pm[pi], s2 = g_ps[pi], x2 = g_px[pi], y2 = g_py[pi], z2 = g_pz[pi];
        float nm = fmaxf(m, m2);
        float a1 = __expf(m - nm), a2 = __expf(m2 - nm);
        s = s*a1 + s2*a2; x = x*a1 + x2*a2; y = y*a1 + y2*a2; z = z*a1 + z2*a2;
        m = nm;
    }
    float inv = 1.f / s;
    g_verts12[(size_t)i*3 + 0] = x*inv;
    g_verts12[(size_t)i*3 + 1] = y*inv;
    g_verts12[(size_t)i*3 + 2] = z*inv;
}

// ---------------- K3: self_rec (SoA + float4 candidate groups) ----------------
__global__ void __launch_bounds__(256) k3_selfrec(const float* __restrict__ verts2){
    __shared__ __align__(16) float sx[K3CH+4];
    __shared__ __align__(16) float sy[K3CH+4];
    __shared__ __align__(16) float sz[K3CH+4];
    int b = blockIdx.y;
    int part = threadIdx.x & 3;
    int nl = threadIdx.x >> 2;
    int n = blockIdx.x*64 + nl;
    bool valid = n < NPTS;
    float vx=0.f, vy=0.f, vz=0.f;
    if (valid){
        vx = g_verts12[((size_t)b*NPTS + n)*3 + 0];
        vy = g_verts12[((size_t)b*NPTS + n)*3 + 1];
        vz = g_verts12[((size_t)b*NPTS + n)*3 + 2];
    }
    const float* v2 = verts2 + (size_t)b*NPTS*3;
    float best = 3.4e38f;
    for (int m0 = 0; m0 < NPTS; m0 += K3CH){
        int cnt = min(K3CH, NPTS - m0);
        __syncthreads();
        for (int i = threadIdx.x; i < cnt; i += 256){
            sx[i] = v2[(m0+i)*3]; sy[i] = v2[(m0+i)*3+1]; sz[i] = v2[(m0+i)*3+2];
        }
        if (threadIdx.x < 4){
            sx[cnt+threadIdx.x] = 1e30f; sy[cnt+threadIdx.x] = 1e30f; sz[cnt+threadIdx.x] = 1e30f;
        }
        __syncthreads();
        int ng = (cnt + 3) >> 2;
        for (int g = part; g < ng; g += 4){
            float4 X = *(const float4*)(sx + 4*g);
            float4 Y = *(const float4*)(sy + 4*g);
            float4 Z = *(const float4*)(sz + 4*g);
            float dx0 = vx-X.x, dy0 = vy-Y.x, dz0 = vz-Z.x;
            float dx1 = vx-X.y, dy1 = vy-Y.y, dz1 = vz-Z.y;
            float dx2 = vx-X.z, dy2 = vy-Y.z, dz2 = vz-Z.z;
            float dx3 = vx-X.w, dy3 = vy-Y.w, dz3 = vz-Z.w;
            float d0 = fmaf(dx0,dx0, fmaf(dy0,dy0, dz0*dz0));
            float d1 = fmaf(dx1,dx1, fmaf(dy1,dy1, dz1*dz1));
            float d2 = fmaf(dx2,dx2, fmaf(dy2,dy2, dz2*dz2));
            float d3 = fmaf(dx3,dx3, fmaf(dy3,dy3, dz3*dz3));
            best = fminf(best, fminf(fminf(d0,d1), fminf(d2,d3)));
        }
    }
    best = fminf(best, __shfl_xor_sync(0xffffffffu, best, 1));
    best = fminf(best, __shfl_xor_sync(0xffffffffu, best, 2));
    float contrib = (part == 0 && valid) ? best : 0.f;
    __syncthreads();
    block_sum_atomic(contrib, &g_self_sum);
}

// ---------------- K4: top-10 nearest neighbors (SoA + group prefilter) ----------------
__global__ void __launch_bounds__(256) k4_topk(const float* __restrict__ verts1){
    __shared__ __align__(16) float sx[K3CH+4];
    __shared__ __align__(16) float sy[K3CH+4];
    __shared__ __align__(16) float sz[K3CH+4];
    __shared__ float smval[256][10];
    __shared__ int   smidx[256][10];
    int b = blockIdx.y;
    int part = threadIdx.x & 3;
    int nl = threadIdx.x >> 2;
    int n = blockIdx.x*64 + nl;
    const float* v1 = verts1 + (size_t)b*NPTS*3;
    float vx=0.f, vy=0.f, vz=0.f;
    if (n < NPTS){ vx = v1[3*n]; vy = v1[3*n+1]; vz = v1[3*n+2]; }
    float val[10]; int idx[10];
    #pragma unroll
    for (int q = 0; q < 10; q++){ val[q] = 3.4e38f; idx[q] = 0; }
    for (int m0 = 0; m0 < NPTS; m0 += K3CH){
        int cnt = min(K3CH, NPTS - m0);
        __syncthreads();
        for (int i = threadIdx.x; i < cnt; i += 256){
            sx[i] = v1[(m0+i)*3]; sy[i] = v1[(m0+i)*3+1]; sz[i] = v1[(m0+i)*3+2];
        }
        if (threadIdx.x < 4){
            sx[cnt+threadIdx.x] = 1e30f; sy[cnt+threadIdx.x] = 1e30f; sz[cnt+threadIdx.x] = 1e30f;
        }
        __syncthreads();
        int ng = (cnt + 3) >> 2;
        for (int g = part; g < ng; g += 4){
            float4 X = *(const float4*)(sx + 4*g);
            float4 Y = *(const float4*)(sy + 4*g);
            float4 Z = *(const float4*)(sz + 4*g);
            float dx0 = vx-X.x, dy0 = vy-Y.x, dz0 = vz-Z.x;
            float dx1 = vx-X.y, dy1 = vy-Y.y, dz1 = vz-Z.y;
            float dx2 = vx-X.z, dy2 = vy-Y.z, dz2 = vz-Z.z;
            float dx3 = vx-X.w, dy3 = vy-Y.w, dz3 = vz-Z.w;
            float d0 = fmaf(dx0,dx0, fmaf(dy0,dy0, dz0*dz0));
            float d1 = fmaf(dx1,dx1, fmaf(dy1,dy1, dz1*dz1));
            float d2 = fmaf(dx2,dx2, fmaf(dy2,dy2, dz2*dz2));
            float d3 = fmaf(dx3,dx3, fmaf(dy3,dy3, dz3*dz3));
            float gm = fminf(fminf(d0,d1), fminf(d2,d3));
            if (gm < val[9]){
                float ds[4]; ds[0]=d0; ds[1]=d1; ds[2]=d2; ds[3]=d3;
                #pragma unroll
                for (int k = 0; k < 4; k++){
                    if (ds[k] < val[9]){
                        float cv = ds[k]; int ci = m0 + 4*g + k;
                        #pragma unroll
                        for (int q = 0; q < 10; q++){
                            if (cv < val[q]){
                                float tv = val[q]; int ti = idx[q];
                                val[q] = cv; idx[q] = ci; cv = tv; ci = ti;
                            }
                        }
                    }
                }
            }
        }
    }
    #pragma unroll
    for (int q = 0; q < 10; q++){ smval[threadIdx.x][q] = val[q]; smidx[threadIdx.x][q] = idx[q]; }
    __syncthreads();
    if (part == 0 && n < NPTS){
        int h0=0,h1=0,h2=0,h3=0;
        int base = threadIdx.x;
        int out = (b*NPTS + n)*KNN;
        #pragma unroll
        for (int q = 0; q < 10; q++){
            float b0 = smval[base][h0],   b1 = smval[base+1][h1];
            float b2 = smval[base+2][h2], b3 = smval[base+3][h3];
            float mm = fminf(fminf(b0,b1), fminf(b2,b3));
            int chosen;
            if (mm == b0){ chosen = smidx[base][h0];   h0++; }
            else if (mm == b1){ chosen = smidx[base+1][h1]; h1++; }
            else if (mm == b2){ chosen = smidx[base+2][h2]; h2++; }
            else { chosen = smidx[base+3][h3]; h3++; }
            g_idx11[out + q] = chosen;
        }
    }
}

// ---------------- K5: deform feature MSE (warp-per-point) ----------------
__global__ void __launch_bounds__(256) k5_deform(const float* __restrict__ feat1){
    int w = threadIdx.x >> 5, lane = threadIdx.x & 31;
    int base = blockIdx.x*64 + w*8;
    float acc = 0.f;
    #pragma unroll
    for (int p = 0; p < 8; p++){
        int bn = base + p;
        if (bn < BATCH*NPTS){
            int b = bn / NPTS, n = bn - b*NPTS;
            const float* f1 = feat1 + (size_t)b*NPTS*CDIM;
            float4 fc = *(const float4*)(f1 + (size_t)n*CDIM + lane*4);
            #pragma unroll
            for (int q = 0; q < KNN; q++){
                int m = g_idx11[bn*KNN + q];
                float4 fm = *(const float4*)(f1 + (size_t)m*CDIM + lane*4);
                float d0 = fm.x - fc.x, d1 = fm.y - fc.y;
                float d2 = fm.z - fc.z, d3 = fm.w - fc.w;
                acc = fmaf(d0,d0, acc); acc = fmaf(d1,d1, acc);
                acc = fmaf(d2,d2, acc); acc = fmaf(d3,d3, acc);
            }
        }
    }
    block_sum_atomic(acc, &g_deform_sum);
}

// ---------------- K6: per-batch xy min/max ----------------
__global__ void __launch_bounds__(256) k6_ptminmax(const float* __restrict__ verts2){
    __shared__ float r0[8], r1[8], r2[8], r3[8];
    int tb = blockIdx.y;
    int tensor = tb >> 2, b = tb & 3;
    const float* p = tensor ? (verts2 + (size_t)b*NPTS*3) : (g_verts12 + (size_t)b*NPTS*3);
    int i = blockIdx.x*256 + threadIdx.x;
    float mnx = 1e30f, mny = 1e30f, mxx = -1e30f, mxy = -1e30f;
    if (i < NPTS){ mnx = mxx = p[3*i]; mny = mxy = p[3*i+1]; }
    int lane = threadIdx.x & 31, w = threadIdx.x >> 5;
    #pragma unroll
    for (int o = 16; o; o >>= 1){
        mnx = fminf(mnx, __shfl_xor_sync(0xffffffffu, mnx, o));
        mny = fminf(mny, __shfl_xor_sync(0xffffffffu, mny, o));
        mxx = fmaxf(mxx, __shfl_xor_sync(0xffffffffu, mxx, o));
        mxy = fmaxf(mxy, __shfl_xor_sync(0xffffffffu, mxy, o));
    }
    if (!lane){ r0[w] = mnx; r1[w] = mny; r2[w] = mxx; r3[w] = mxy; }
    __syncthreads();
    if (w == 0){
        mnx = (lane < 8) ? r0[lane] : 1e30f;
        mny = (lane < 8) ? r1[lane] : 1e30f;
        mxx = (lane < 8) ? r2[lane] : -1e30f;
        mxy = (lane < 8) ? r3[lane] : -1e30f;
        #pragma unroll
        for (int o = 4; o; o >>= 1){
            mnx = fminf(mnx, __shfl_xor_sync(0xffffffffu, mnx, o));
            mny = fminf(mny, __shfl_xor_sync(0xffffffffu, mny, o));
            mxx = fmaxf(mxx, __shfl_xor_sync(0xffffffffu, mxx, o));
            mxy = fmaxf(mxy, __shfl_xor_sync(0xffffffffu, mxy, o));
        }
        if (!lane){
            atomicMin(&g_pminE[tensor][b][0], fenc(mnx));
            atomicMin(&g_pminE[tensor][b][1], fenc(mny));
            atomicMax(&g_pmaxE[tensor][b][0], fenc(mxx));
            atomicMax(&g_pmaxE[tensor][b][1], fenc(mxy));
        }
    }
}

// ---------------- K7: per-batch int min/max of grid indices ----------------
__global__ void __launch_bounds__(256) k7_idxminmax(const float* __restrict__ verts2){
    __shared__ int r0[8], r1[8], r2[8], r3[8];
    int tb = blockIdx.y;
    int tensor = tb >> 2, b = tb & 3;
    const float* p = tensor ? (verts2 + (size_t)b*NPTS*3) : (g_verts12 + (size_t)b*NPTS*3);
    float minx = fdec(g_pminE[tensor][b][0]);
    float miny = fdec(g_pminE[tensor][b][1]);
    float maxx = fdec(g_pmaxE[tensor][b][0]);
    float maxy = fdec(g_pmaxE[tensor][b][1]);
    float gs = __fdiv_rn(fmaxf(maxx - minx, maxy - miny), 221.0f);
    int i = blockIdx.x*256 + threadIdx.x;
    int mnx = 0x7FFFFFFF, mny = 0x7FFFFFFF;
    int mxx = (int)0x80000000, mxy = (int)0x80000000;
    if (i < NPTS){
        int ix = (int)floorf(__fdiv_rn(p[3*i]   - minx, gs));
        int iy = (int)floorf(__fdiv_rn(p[3*i+1] - miny, gs));
        mnx = mxx = ix; mny = mxy = iy;
    }
    int lane = threadIdx.x & 31, w = threadIdx.x >> 5;
    #pragma unroll
    for (int o = 16; o; o >>= 1){
        mnx = min(mnx, __shfl_xor_sync(0xffffffffu, mnx, o));
        mny = min(mny, __shfl_xor_sync(0xffffffffu, mny, o));
        mxx = max(mxx, __shfl_xor_sync(0xffffffffu, mxx, o));
        mxy = max(mxy, __shfl_xor_sync(0xffffffffu, mxy, o));
    }
    if (!lane){ r0[w] = mnx; r1[w] = mny; r2[w] = mxx; r3[w] = mxy; }
    __syncthreads();
    if (w == 0){
        mnx = (lane < 8) ? r0[lane] : 0x7FFFFFFF;
        mny = (lane < 8) ? r1[lane] : 0x7FFFFFFF;
        mxx = (lane < 8) ? r2[lane] : (int)0x80000000;
        mxy = (lane < 8) ? r3[lane] : (int)0x80000000;
        #pragma unroll
        for (int o = 4; o; o >>= 1){
            mnx = min(mnx, __shfl_xor_sync(0xffffffffu, mnx, o));
            mny = min(mny, __shfl_xor_sync(0xffffffffu, mny, o));
            mxx = max(mxx, __shfl_xor_sync(0xffffffffu, mxx, o));
            mxy = max(mxy, __shfl_xor_sync(0xffffffffu, mxy, o));
        }
        if (!lane){
            atomicMin(&g_iminI[tensor][b][0], mnx);
            atomicMin(&g_iminI[tensor][b][1], mny);
            atomicMax(&g_imaxI[tensor][b][0], mxx);
            atomicMax(&g_imaxI[tensor][b][1], mxy);
        }
    }
}

// ---------------- K8: scatter z into images ----------------
__global__ void __launch_bounds__(256) k8_scatter(const float* __restrict__ verts2){
    int tb = blockIdx.y;
    int tensor = tb >> 2, b = tb & 3;
    const float* p = tensor ? (verts2 + (size_t)b*NPTS*3) : (g_verts12 + (size_t)b*NPTS*3);
    int i = blockIdx.x*256 + threadIdx.x;
    if (i >= NPTS) return;
    float minx = fdec(g_pminE[tensor][b][0]);
    float miny = fdec(g_pminE[tensor][b][1]);
    float maxx = fdec(g_pmaxE[tensor][b][0]);
    float maxy = fdec(g_pmaxE[tensor][b][1]);
    float gs = __fdiv_rn(fmaxf(maxx - minx, maxy - miny), 221.0f);
    int ix = (int)floorf(__fdiv_rn(p[3*i]   - minx, gs));
    int iy = (int)floorf(__fdiv_rn(p[3*i+1] - miny, gs));
    float z = p[3*i+2];
    int cx = (g_imaxI[tensor][b][0] + g_iminI[tensor][b][0] + 2) >> 1;
    int cy = (g_imaxI[tensor][b][1] + g_iminI[tensor][b][1] + 2) >> 1;
    int ox = 111 - cx, oy = 111 - cy;
    float* img = g_img[tensor] + b*IMGSZ;
    #pragma unroll
    for (int t2 = 0; t2 < 25; t2++){
        int du = t2 / 5;
        int dv = t2 - du*5;
        int uu = ix + du - 1 + ox;
        int vv = iy + dv - 1 + oy;
        uu += (uu < 0) - (uu > IMG-1);
        vv += (vv < 0) - (vv > IMG-1);
        uu = max(0, min(IMG-1, uu));
        vv = max(0, min(IMG-1, vv));
        atomicAdd(&img[uu*IMG + vv], z);
    }
}

// ---------------- K9: image MSE ----------------
__global__ void __launch_bounds__(256) k9_imgloss(){
    int i = blockIdx.x*256 + threadIdx.x;
    float d = 0.f;
    if (i < BATCH*IMGSZ){
        float a = g_img[0][i], b2 = g_img[1][i];
        float s1 = 1.f/(1.f + __expf(-a));
        float s2 = 1.f/(1.f + __expf(-b2));
        float df = s1 - s2;
        d = df*df;
    }
    block_sum_atomic(d, &g_img_sum);
}

// ---------------- K10: finalize ----------------
__global__ void k10_final(float* out){
    if (threadIdx.x == 0 && blockIdx.x == 0){
        double self_l = g_self_sum / (double)(BATCH*NPTS);
        double def_l  = g_deform_sum / ((double)BATCH*NPTS*KNN*CDIM);
        double img_l  = g_img_sum / ((double)BATCH*IMGSZ);
        out[0] = (float)(self_l + img_l + def_l);
    }
}

// ---------------- launch ----------------
extern "C" void kernel_launch(void* const* d_in, const int* in_sizes, int n_in,
                              void* d_out, int out_size){
    const float* verts1 = (const float*)d_in[0];
    const float* verts2 = (const float*)d_in[1];
    const float* feat1  = (const float*)d_in[2];
    const float* feat2  = (const float*)d_in[3];
    float* out = (float*)d_out;

    cudaFuncSetAttribute(k2_softmax_mma, cudaFuncAttributeMaxDynamicSharedMemorySize, K2SMEM);

    k_init<<<1568, 256>>>();
    kprep<<<4995, 256>>>(feat1, feat2);
    k1_norms<<<4995, 256>>>(feat1, feat2);
    k2_softmax_mma<<<dim3(MTILES, NSPLIT, BATCH), K2_THREADS, K2SMEM>>>(verts2);
    k2b_merge<<<(BATCH*NPTS + 255)/256, 256>>>();
    k3_selfrec<<<dim3((NPTS+63)/64, BATCH), 256>>>(verts2);
    k4_topk<<<dim3((NPTS+63)/64, BATCH), 256>>>(verts1);
    k5_deform<<<(BATCH*NPTS + 63)/64, 256>>>(feat1);
    k6_ptminmax<<<dim3((NPTS+255)/256, 2*BATCH), 256>>>(verts2);
    k7_idxminmax<<<dim3((NPTS+255)/256, 2*BATCH), 256>>>(verts2);
    k8_scatter<<<dim3((NPTS+255)/256, 2*BATCH), 256>>>(verts2);
    k9_imgloss<<<(BATCH*IMGSZ+255)/256, 256>>>();
    k10_final<<<1, 32>>>(out);
}